// round 12
// baseline (speedup 1.0000x reference)
#include <cuda_runtime.h>
#include <cuda_bf16.h>

#define BB 2
#define LLEN 2048
#define MM 16
#define KNN 32
#define NRES (BB*LLEN)            // 4096
#define NEDGE (NRES*KNN)          // 131072
#define NROW (NRES*MM)            // 65536

static const size_t V_OFF  = 0;
static const size_t E_OFF  = (size_t)NROW*128;                  // 8388608
static const size_t EI_OFF = E_OFF + (size_t)NEDGE*128;         // 25165824
static const size_t YN_OFF = EI_OFF + (size_t)NEDGE;            // 25296896
static const size_t YE_OFF = YN_OFF + (size_t)NROW*128;         // 33685504
static const size_t YM_OFF = YE_OFF + (size_t)NRES*MM*MM*128;   // 167903232

typedef unsigned long long ull;

// ---------------- device scratch ----------------
__device__ float g_atoms[NRES*15];
__device__ float g_cax[NRES*3];
__device__ int   g_eidx[NEDGE];
__device__ float g_dnb[NEDGE];
__device__ float g_WeT[416*128];                 // W_edge^T [f][n] (for k_fuse consumers)
__device__ __align__(16) ull g_WeTd[416*128];    // dup'd: each channel value in both f32x2 lanes
__device__ float g_WdTF[148*128];                // W_down^T full [f][n]
__device__ __align__(16) ull g_WdTd[96*128];     // dup'd compact W_down rows
__device__ float g_WynT[147*128];                // W_yn^T [f][c]
__device__ float g_Tpos[66*128];                 // fused pos table
__device__ float g_Wfuse[147*128];               // Wt^T . Wd[:,80:144]^T
__device__ float g_btf[128];                     // fused bias

// pairs (excluding leading D_neighbors block); atoms: N=0,Ca=1,C=2,O=3,Cb=4
__constant__ int c_PA24[24] = {0,2,3,4, 1,1,1,1, 0,0,0, 4,4, 3, 0,2,3,4, 2,3,4, 2,3, 2};
__constant__ int c_PB24[24] = {0,2,3,4, 0,2,3,4, 2,3,4, 2,3, 2, 1,1,1,1, 0,0,0, 4,4, 3};

// ---------------- f32x2 helpers ----------------
__device__ __forceinline__ ull pack2(float s) {
    ull r; asm("mov.b64 %0, {%1, %1};" : "=l"(r) : "r"(__float_as_uint(s))); return r;
}
__device__ __forceinline__ void ffma2(ull& a, ull s, ull w) {
    asm("fma.rn.f32x2 %0, %1, %2, %0;" : "+l"(a) : "l"(s), "l"(w));
}
__device__ __forceinline__ float2 unpack2(ull a) {
    unsigned lo, hi; asm("mov.b64 {%0, %1}, %2;" : "=r"(lo), "=r"(hi) : "l"(a));
    return make_float2(__uint_as_float(lo), __uint_as_float(hi));
}
__device__ __forceinline__ float4 ln128(float4 a, float4 g, float4 be) {
    float s  = a.x + a.y + a.z + a.w;
    float ss = fmaf(a.x,a.x, fmaf(a.y,a.y, fmaf(a.z,a.z, a.w*a.w)));
#pragma unroll
    for (int o = 16; o; o >>= 1) {
        s  += __shfl_xor_sync(0xffffffffu, s,  o);
        ss += __shfl_xor_sync(0xffffffffu, ss, o);
    }
    float mu   = s * 0.0078125f;
    float var  = ss * 0.0078125f - mu*mu;
    float rstd = rsqrtf(var + 1e-5f);
    float4 o4;
    o4.x = (a.x-mu)*rstd*g.x + be.x;
    o4.y = (a.y-mu)*rstd*g.y + be.y;
    o4.z = (a.z-mu)*rstd*g.z + be.z;
    o4.w = (a.w-mu)*rstd*g.w + be.w;
    return o4;
}

// 16 RBF values with 4 exps: anchor at nearest mu, geometric ratio chain.
__device__ __forceinline__ void rbf16(float D, float* dst, int stride) {
    const float DLT = 1.3333333333333333f;
    const float IS2 = 0.64f;
    const float C1  = 1.7066666666666668f;
    const float C2  = 1.1377777777777778f;
    float u = (D - 2.0f) * 0.75f;
    int rs = __float2int_rn(u);
    rs = rs < 0 ? 0 : (rs > 15 ? 15 : rs);
    float x = D - (2.0f + DLT * (float)rs);
    float peak  = __expf(-x*x*IS2);
    float fup   = __expf( C1*x - C2);
    float fdn   = __expf(-C1*x - C2);
    float decay = __expf(-2.0f*C2);
    float v = peak;
    dst[rs*stride] = v;
    float f = fup;
    for (int r = rs+1; r < 16; r++) { v *= f; dst[r*stride] = v; f *= decay; }
    v = peak; f = fdn;
    for (int r = rs-1; r >= 0; r--) { v *= f; dst[r*stride] = v; f *= decay; }
}

// ---------------- prep kernels ----------------
__global__ void k_atoms(const float* __restrict__ X) {
    int r = blockIdx.x*blockDim.x + threadIdx.x;
    if (r >= NRES) return;
    const float* x = X + (size_t)r*12;
    float nx=x[0],ny=x[1],nz=x[2], cax=x[3],cay=x[4],caz=x[5];
    float cxx=x[6],cyy=x[7],czz=x[8], ox=x[9],oy=x[10],oz=x[11];
    float bx=cax-nx, by=cay-ny, bz=caz-nz;
    float ccx=cxx-cax, ccy=cyy-cay, ccz=czz-caz;
    float ax=by*ccz-bz*ccy, ay=bz*ccx-bx*ccz, az=bx*ccy-by*ccx;
    float cbx=-0.58273431f*ax+0.56802827f*bx-0.54067466f*ccx+cax;
    float cby=-0.58273431f*ay+0.56802827f*by-0.54067466f*ccy+cay;
    float cbz=-0.58273431f*az+0.56802827f*bz-0.54067466f*ccz+caz;
    float* o = g_atoms + (size_t)r*15;
    o[0]=nx;o[1]=ny;o[2]=nz; o[3]=cax;o[4]=cay;o[5]=caz;
    o[6]=cxx;o[7]=cyy;o[8]=czz; o[9]=ox;o[10]=oy;o[11]=oz;
    o[12]=cbx;o[13]=cby;o[14]=cbz;
    g_cax[r*3+0]=cax; g_cax[r*3+1]=cay; g_cax[r*3+2]=caz;
}

__device__ __forceinline__ ull dup_bits(float v) {
    unsigned b = __float_as_uint(v);
    return ((ull)b << 32) | (ull)b;
}

__global__ void k_trans(const float* __restrict__ We, const float* __restrict__ Wd,
                        const float* __restrict__ Wyn) {
    int i = blockIdx.x*blockDim.x + threadIdx.x;
    if (i < 416*128) {
        int f=i>>7, n=i&127;
        float v = We[n*416+f];
        g_WeT[i] = v;
        g_WeTd[i] = dup_bits(v);
        return;
    }
    i -= 416*128;
    if (i < 148*128) { int f=i>>7, n=i&127; g_WdTF[i] = Wd[n*148+f]; return; }
    i -= 148*128;
    if (i < 96*128) {
        int f=i>>7, n=i&127;
        float v = 0.0f;
        if (f < 80) v = Wd[n*148+f];
        else if (f < 84) v = Wd[n*148+144+(f-80)];
        g_WdTd[i] = dup_bits(v);
        return;
    }
    i -= 96*128;
    if (i < 147*128) { int f=i>>7, c=i&127; g_WynT[i] = Wyn[c*147+f]; }
}

__global__ void k_fuse(const float* __restrict__ Wp, const float* __restrict__ bp,
                       const float* __restrict__ We, const float* __restrict__ Wt,
                       const float* __restrict__ bt, const float* __restrict__ bd) {
    int i = blockIdx.x*blockDim.x + threadIdx.x;
    if (i < 66*128) {
        int d = i>>7, n = i&127;
        float s = 0.0f;
        for (int c = 0; c < 16; c++) s = fmaf(Wp[c*66+d] + bp[c], We[n*416+c], s);
        g_Tpos[i] = s; return;
    }
    i -= 66*128;
    if (i < 147*128) {
        int f = i>>7, n = i&127;
        float s = 0.0f;
        for (int c = 0; c < 64; c++) s = fmaf(Wt[c*147+f], g_WdTF[(80+c)*128+n], s);
        g_Wfuse[i] = s; return;
    }
    i -= 147*128;
    if (i < 128) {
        float s = bd[i];
        for (int c = 0; c < 64; c++) s = fmaf(bt[c], g_WdTF[(80+c)*128+i], s);
        g_btf[i] = s;
    }
}

// ---------------- top-K neighbors: histogram pre-filter + exact warp selection ----------------
__global__ __launch_bounds__(256) void k_topk(const float* __restrict__ mask,
                                              float* __restrict__ out) {
    int row = blockIdx.x, b = row >> 11, t = threadIdx.x;
    int lane = t & 31, w = t >> 5;
    __shared__ float smax[8];
    __shared__ unsigned hist[256];
    __shared__ float pd[2048];
    __shared__ int   pj[2048];
    __shared__ int   scnt;
    __shared__ int   sthr;

    hist[t] = 0u;
    if (t == 0) scnt = 0;

    float cx = g_cax[row*3], cy = g_cax[row*3+1], cz = g_cax[row*3+2];
    float mi = mask[row];
    float dv[8], m2v[8];
    float lmax = -1e30f;
#pragma unroll
    for (int q = 0; q < 8; q++) {
        int jr = b*LLEN + t + (q<<8);
        float dx = cx - g_cax[jr*3], dy = cy - g_cax[jr*3+1], dz = cz - g_cax[jr*3+2];
        float dist = sqrtf(dx*dx + dy*dy + dz*dz + 1e-6f);
        float m2 = mi * mask[jr];
        dv[q] = m2 * dist; m2v[q] = m2;
        lmax = fmaxf(lmax, dv[q]);
    }
#pragma unroll
    for (int o = 16; o; o >>= 1) lmax = fmaxf(lmax, __shfl_xor_sync(0xffffffffu, lmax, o));
    if (lane == 0) smax[w] = lmax;
    __syncthreads();
    float dmax = fmaxf(fmaxf(fmaxf(smax[0],smax[1]),fmaxf(smax[2],smax[3])),
                       fmaxf(fmaxf(smax[4],smax[5]),fmaxf(smax[6],smax[7])));
    float inv = 256.0f / (dmax + 1e-6f);
#pragma unroll
    for (int q = 0; q < 8; q++) {
        dv[q] += (1.0f - m2v[q]) * dmax;
        int bq = (int)(dv[q] * inv);
        bq = bq < 0 ? 0 : (bq > 255 ? 255 : bq);
        atomicAdd(&hist[bq], 1u);
    }
    __syncthreads();

    if (w == 0) {
        unsigned s = 0;
#pragma unroll
        for (int k = 0; k < 8; k++) s += hist[lane*8 + k];
        unsigned scan = s;
#pragma unroll
        for (int o = 1; o < 32; o <<= 1) {
            unsigned v = __shfl_up_sync(0xffffffffu, scan, o);
            if (lane >= o) scan += v;
        }
        unsigned ballot = __ballot_sync(0xffffffffu, scan >= KNN);
        int fl = __ffs(ballot) - 1;
        if (lane == fl) {
            unsigned cum = scan - s;
            int bt_ = lane*8;
            for (int k = 0; k < 8; k++) {
                cum += hist[lane*8 + k];
                if (cum >= KNN) { bt_ = lane*8 + k; break; }
            }
            sthr = bt_;
        }
    }
    __syncthreads();

    int thr = sthr;
#pragma unroll
    for (int q = 0; q < 8; q++) {
        int bq = (int)(dv[q] * inv);
        bq = bq < 0 ? 0 : (bq > 255 ? 255 : bq);
        if (bq <= thr) {
            int p = atomicAdd(&scnt, 1);
            pd[p] = dv[q];
            pj[p] = t + (q<<8);
        }
    }
    __syncthreads();

    if (w == 0) {
        int n = scnt;
        for (int it = 0; it < KNN; it++) {
            float bv = 3e38f; int bj = 0x7fffffff; int bp = -1;
            for (int i = lane; i < n; i += 32) {
                float v = pd[i]; int j = pj[i];
                if (v < bv || (v == bv && j < bj)) { bv = v; bj = j; bp = i; }
            }
            float rv = bv; int rj = bj;
#pragma unroll
            for (int o = 16; o; o >>= 1) {
                float ov = __shfl_xor_sync(0xffffffffu, rv, o);
                int   oj = __shfl_xor_sync(0xffffffffu, rj, o);
                if (ov < rv || (ov == rv && oj < rj)) { rv = ov; rj = oj; }
            }
            if (bp >= 0 && rv == bv && rj == bj) pd[bp] = 3e38f;
            if (lane == 0) {
                g_eidx[(size_t)row*KNN + it] = rj;
                g_dnb [(size_t)row*KNN + it] = rv;
                out[EI_OFF + (size_t)row*KNN + it] = (float)rj;
            }
            __syncwarp();
        }
    }
}

// ---------------- Edge: features + GEMM(400->128, dup'd W via L1/L2) + Tpos + LN ----------------
#define EFEAT_ROWS 144
#define EDGE_SMF (EFEAT_ROWS*64 + 32 + 960 + 64 + 64 + 64)   // 10400 floats = 41.6KB
__global__ __launch_bounds__(256, 4) void k_edge(
    const int* __restrict__ R_idx, const int* __restrict__ chains,
    const float* __restrict__ b_edge, const float* __restrict__ g_edge,
    const float* __restrict__ be_edge, float* __restrict__ out) {
    extern __shared__ float sm[];
    float* feats = sm;                       // [144][64]
    float* ai    = sm + EFEAT_ROWS*64;       // 32
    float* aj    = ai + 32;                  // [64][15]
    float* dnb   = aj + 960;                 // 64
    int*   sJ    = (int*)(dnb + 64);         // 64
    int*   sdc   = sJ + 64;                  // 64

    int t = threadIdx.x;
    int r0 = blockIdx.x * 2;
    int b  = r0 >> 11;
    int ebase = blockIdx.x * 64;
    int lane = t & 31, w = t >> 5;

    if (t < 30) ai[t] = g_atoms[r0*15 + t];
    if (t < 64) { sJ[t] = g_eidx[ebase + t]; dnb[t] = g_dnb[ebase + t]; }
    __syncthreads();
    for (int k = t; k < 960; k += 256) {
        int e = k / 15, c = k % 15;
        aj[k] = g_atoms[(size_t)(b*LLEN + sJ[e])*15 + c];
    }
    if (t < 64) {
        int ig = r0 + (t >> 5);
        int jg = b*LLEN + sJ[t];
        int off = R_idx[ig] - R_idx[jg];
        int ec  = (chains[ig] == chains[jg]);
        int d = off + 32; d = d < 0 ? 0 : (d > 64 ? 64 : d);
        sdc[t] = ec ? d : 65;
    }
    __syncthreads();

    ull acc[16];
    {
        float4 b4 = ((const float4*)b_edge)[lane];
        ull b0 = pack2(b4.x), b1 = pack2(b4.y), b2 = pack2(b4.z), b3 = pack2(b4.w);
#pragma unroll
        for (int p = 0; p < 4; p++) { acc[p*4]=b0; acc[p*4+1]=b1; acc[p*4+2]=b2; acc[p*4+3]=b3; }
    }

    int pbase = 0;
    for (int ph = 0; ph < 3; ph++) {
        int P = ph ? 8 : 9;
        {
            int e = t & 63, psub = t >> 6;
            const float* A  = ai + (e >> 5) * 15;
            const float* Bv = aj + e * 15;
            for (int p = psub; p < P; p += 4) {
                int gp = pbase + p;
                float D;
                if (gp == 0) D = dnb[e];
                else {
                    int pa = c_PA24[gp-1]*3, pb = c_PB24[gp-1]*3;
                    float dx=A[pa]-Bv[pb], dy=A[pa+1]-Bv[pb+1], dz=A[pa+2]-Bv[pb+2];
                    D = sqrtf(dx*dx + dy*dy + dz*dz + 1e-6f);
                }
                rbf16(D, &feats[(p*16)*64 + e], 64);
            }
        }
        __syncthreads();
        for (int kc = 0; kc < P; kc++) {
            const ulonglong2* Wr = (const ulonglong2*)(g_WeTd + (size_t)(pbase+kc+1)*16*128);
            const float* fb = feats + (kc*16)*64 + 8*w;
#pragma unroll
            for (int fi = 0; fi < 16; fi++) {
                ulonglong2 wa = __ldg(&Wr[fi*64 + 2*lane]);
                ulonglong2 wb = __ldg(&Wr[fi*64 + 2*lane + 1]);
                ulonglong2 f01 = *(const ulonglong2*)&fb[fi*64];
                ulonglong2 f23 = *(const ulonglong2*)&fb[fi*64 + 4];
                ffma2(acc[0],  f01.x, wa.x); ffma2(acc[1],  f01.x, wa.y);
                ffma2(acc[2],  f01.x, wb.x); ffma2(acc[3],  f01.x, wb.y);
                ffma2(acc[4],  f01.y, wa.x); ffma2(acc[5],  f01.y, wa.y);
                ffma2(acc[6],  f01.y, wb.x); ffma2(acc[7],  f01.y, wb.y);
                ffma2(acc[8],  f23.x, wa.x); ffma2(acc[9],  f23.x, wa.y);
                ffma2(acc[10], f23.x, wb.x); ffma2(acc[11], f23.x, wb.y);
                ffma2(acc[12], f23.y, wa.x); ffma2(acc[13], f23.y, wa.y);
                ffma2(acc[14], f23.y, wb.x); ffma2(acc[15], f23.y, wb.y);
            }
        }
        __syncthreads();
        pbase += P;
    }

    float4 g4  = ((const float4*)g_edge)[lane];
    float4 be4 = ((const float4*)be_edge)[lane];
    float4* o4 = (float4*)(out + E_OFF);
#pragma unroll
    for (int p = 0; p < 4; p++) {
        float2 u0 = unpack2(acc[p*4]);
        float2 u1 = unpack2(acc[p*4+1]);
        float2 u2 = unpack2(acc[p*4+2]);
        float2 u3 = unpack2(acc[p*4+3]);
        int e0 = 8*w + 2*p, e1 = e0 + 1;
        float4 tp0 = ((const float4*)g_Tpos)[sdc[e0]*32 + lane];
        float4 tp1 = ((const float4*)g_Tpos)[sdc[e1]*32 + lane];
        float4 a0 = make_float4(u0.x+tp0.x, u1.x+tp0.y, u2.x+tp0.z, u3.x+tp0.w);
        float4 a1 = make_float4(u0.y+tp1.x, u1.y+tp1.y, u2.y+tp1.z, u3.y+tp1.w);
        float4 r0v = ln128(a0, g4, be4);
        float4 r1v = ln128(a1, g4, be4);
        o4[(size_t)(ebase+e0)*32 + lane] = r0v;
        o4[(size_t)(ebase+e1)*32 + lane] = r1v;
    }
}

// ---------------- V node: features + GEMM(96->128, dup'd W) + fuse + LN ----------------
#define VN_SMF (96*64 + 64 + 192 + 36 + 192)   // 6628 floats = 26.5KB
__global__ __launch_bounds__(256, 4) void k_vnode(
    const float* __restrict__ Y, const int* __restrict__ Y_t, const int* __restrict__ pt,
    const float* __restrict__ g_node, const float* __restrict__ bn_node,
    float* __restrict__ out) {
    extern __shared__ float sm[];
    float* feats = sm;                    // [96][64]
    float* at    = sm + 96*64;            // [4][15] pad 64
    float* ys    = at + 64;               // [64][3]
    float* fr    = ys + 192;              // [4][9]
    int*   cols  = (int*)(fr + 36);       // [64][3]

    int t = threadIdx.x;
    int bid = blockIdx.x;
    int rbase = bid * 4;
    int rowg0 = bid * 64;
    int lane = t & 31, w = t >> 5;

    if (t < 60) at[t] = g_atoms[(size_t)rbase*15 + t];
    if (t < 192) ys[t] = Y[(size_t)rowg0*3 + t];
    if (t < 64) {
        int yt = Y_t[rowg0 + t];
        cols[t*3+0] = yt;
        cols[t*3+1] = 120 + pt[120 + yt];
        cols[t*3+2] = 139 + pt[240 + yt];
    }
    for (int idx = t; idx < 12*64; idx += 256) feats[84*64 + idx] = 0.0f;
    __syncthreads();
    if (t < 4) {
        const float* A = at + t*15;
        float v1x=A[0]-A[3], v1y=A[1]-A[4], v1z=A[2]-A[5];
        float v2x=A[6]-A[3], v2y=A[7]-A[4], v2z=A[8]-A[5];
        float n1 = sqrtf(v1x*v1x+v1y*v1y+v1z*v1z) + 1e-8f;
        float e1x=v1x/n1, e1y=v1y/n1, e1z=v1z/n1;
        float d12 = e1x*v2x + e1y*v2y + e1z*v2z;
        float ux=v2x-e1x*d12, uy=v2y-e1y*d12, uz=v2z-e1z*d12;
        float n2 = sqrtf(ux*ux+uy*uy+uz*uz) + 1e-8f;
        float e2x=ux/n2, e2y=uy/n2, e2z=uz/n2;
        float e3x=e1y*e2z-e1z*e2y, e3y=e1z*e2x-e1x*e2z, e3z=e1x*e2y-e1y*e2x;
        float* F = fr + t*9;
        F[0]=e1x;F[1]=e1y;F[2]=e1z; F[3]=e2x;F[4]=e2y;F[5]=e2z; F[6]=e3x;F[7]=e3y;F[8]=e3z;
    }
    {
        int row = t & 63, res = row >> 4;
        const float* yy = ys + row*3;
        for (int p = t >> 6; p < 5; p += 4) {
            const float* A = at + res*15 + p*3;
            float dx=A[0]-yy[0], dy=A[1]-yy[1], dz=A[2]-yy[2];
            float D = sqrtf(dx*dx+dy*dy+dz*dz + 1e-6f);
            rbf16(D, &feats[(p*16)*64 + row], 64);
        }
    }
    __syncthreads();
    if (t < 64) {
        int row = t, res = row >> 4;
        const float* F = fr + res*9;
        float dx = ys[row*3]   - at[res*15+3];
        float dy = ys[row*3+1] - at[res*15+4];
        float dz = ys[row*3+2] - at[res*15+5];
        float lv0 = F[0]*dx+F[1]*dy+F[2]*dz;
        float lv1 = F[3]*dx+F[4]*dy+F[5]*dz;
        float lv2 = F[6]*dx+F[7]*dy+F[8]*dz;
        float rxy  = sqrtf(lv0*lv0 + lv1*lv1 + 1e-8f);
        float rxyz = sqrtf(lv0*lv0 + lv1*lv1 + lv2*lv2) + 1e-8f;
        feats[80*64+row] = lv0/rxy;
        feats[81*64+row] = lv1/rxy;
        feats[82*64+row] = rxy/rxyz;
        feats[83*64+row] = lv2/rxyz;
    }
    __syncthreads();
    ull acc[16];
    {
        float4 b4 = ((const float4*)g_btf)[lane];
        ull b0 = pack2(b4.x), b1 = pack2(b4.y), b2 = pack2(b4.z), b3 = pack2(b4.w);
#pragma unroll
        for (int p = 0; p < 4; p++) { acc[p*4]=b0; acc[p*4+1]=b1; acc[p*4+2]=b2; acc[p*4+3]=b3; }
    }
    for (int kc = 0; kc < 6; kc++) {
        const ulonglong2* Wr = (const ulonglong2*)(g_WdTd + (size_t)kc*16*128);
        const float* fb = feats + (kc*16)*64 + 8*w;
#pragma unroll
        for (int fi = 0; fi < 16; fi++) {
            ulonglong2 wa = __ldg(&Wr[fi*64 + 2*lane]);
            ulonglong2 wb = __ldg(&Wr[fi*64 + 2*lane + 1]);
            ulonglong2 f01 = *(const ulonglong2*)&fb[fi*64];
            ulonglong2 f23 = *(const ulonglong2*)&fb[fi*64 + 4];
            ffma2(acc[0],  f01.x, wa.x); ffma2(acc[1],  f01.x, wa.y);
            ffma2(acc[2],  f01.x, wb.x); ffma2(acc[3],  f01.x, wb.y);
            ffma2(acc[4],  f01.y, wa.x); ffma2(acc[5],  f01.y, wa.y);
            ffma2(acc[6],  f01.y, wb.x); ffma2(acc[7],  f01.y, wb.y);
            ffma2(acc[8],  f23.x, wa.x); ffma2(acc[9],  f23.x, wa.y);
            ffma2(acc[10], f23.x, wb.x); ffma2(acc[11], f23.x, wb.y);
            ffma2(acc[12], f23.y, wa.x); ffma2(acc[13], f23.y, wa.y);
            ffma2(acc[14], f23.y, wb.x); ffma2(acc[15], f23.y, wb.y);
        }
    }
    float4 g4  = ((const float4*)g_node)[lane];
    float4 be4 = ((const float4*)bn_node)[lane];
    float4* o4 = (float4*)(out + V_OFF);
#pragma unroll
    for (int p = 0; p < 4; p++) {
        float2 u0 = unpack2(acc[p*4]);
        float2 u1 = unpack2(acc[p*4+1]);
        float2 u2 = unpack2(acc[p*4+2]);
        float2 u3 = unpack2(acc[p*4+3]);
        int e0 = 8*w + 2*p, e1 = e0 + 1;
        float4 a0 = make_float4(u0.x, u1.x, u2.x, u3.x);
        float4 a1 = make_float4(u0.y, u1.y, u2.y, u3.y);
#pragma unroll
        for (int j = 0; j < 3; j++) {
            float4 q0 = ((const float4*)g_Wfuse)[cols[e0*3+j]*32 + lane];
            float4 q1 = ((const float4*)g_Wfuse)[cols[e1*3+j]*32 + lane];
            a0.x+=q0.x; a0.y+=q0.y; a0.z+=q0.z; a0.w+=q0.w;
            a1.x+=q1.x; a1.y+=q1.y; a1.z+=q1.z; a1.w+=q1.w;
        }
        float4 r0v = ln128(a0, g4, be4);
        float4 r1v = ln128(a1, g4, be4);
        o4[(size_t)(rowg0+e0)*32 + lane] = r0v;
        o4[(size_t)(rowg0+e1)*32 + lane] = r1v;
    }
}

// ---------------- Y_nodes (gather + LN) + Y_m copy ----------------
__global__ __launch_bounds__(256) void k_ynode(
    const float* __restrict__ Y_m, const int* __restrict__ Y_t, const int* __restrict__ pt,
    const float* __restrict__ b_yn, const float* __restrict__ g_yn,
    const float* __restrict__ bn_yn, float* __restrict__ out) {
    int t = threadIdx.x, lane = t & 31, w = t >> 5;
    int row = blockIdx.x*8 + w;
    int yt = Y_t[row];
    int c0 = yt, c1 = 120 + pt[120+yt], c2 = 139 + pt[240+yt];
    float4 a  = ((const float4*)&g_WynT[(size_t)c0*128])[lane];
    float4 a1 = ((const float4*)&g_WynT[(size_t)c1*128])[lane];
    float4 a2 = ((const float4*)&g_WynT[(size_t)c2*128])[lane];
    float4 b4 = ((const float4*)b_yn)[lane];
    a.x += a1.x + a2.x + b4.x;
    a.y += a1.y + a2.y + b4.y;
    a.z += a1.z + a2.z + b4.z;
    a.w += a1.w + a2.w + b4.w;
    float4 g4  = ((const float4*)g_yn)[lane];
    float4 be4 = ((const float4*)bn_yn)[lane];
    float4 r = ln128(a, g4, be4);
    ((float4*)(out + YN_OFF))[(size_t)row*32 + lane] = r;
    if (lane == 0) out[YM_OFF + row] = Y_m[row];
}

// ---------------- Y_edges: symmetric pairs, 16->128 + LN ----------------
__global__ __launch_bounds__(256) void k_yedge(
    const float* __restrict__ Y, const float* __restrict__ W_ye,
    const float* __restrict__ b_ye, const float* __restrict__ g_ye,
    const float* __restrict__ bn_ye, float* __restrict__ out) {
    __shared__ float ys[48];
    __shared__ float rbfs[136*16];
    __shared__ float WyeS[16*128];
    __shared__ int sm1[136], sm2[136];
    int t = threadIdx.x, bl = blockIdx.x;
    if (t < 48) ys[t] = Y[(size_t)bl*48 + t];
    for (int i = t; i < 2048; i += 256) {
        int c = i >> 4, r = i & 15;
        WyeS[r*128 + c] = W_ye[i];
    }
    if (t < 136) {
        int u = t, m1 = 0;
        while (u >= 16 - m1) { u -= 16 - m1; m1++; }
        sm1[t] = m1; sm2[t] = m1 + u;
    }
    __syncthreads();
    if (t < 136) {
        int m1 = sm1[t], m2 = sm2[t];
        float dx = ys[m1*3]-ys[m2*3], dy = ys[m1*3+1]-ys[m2*3+1], dz = ys[m1*3+2]-ys[m2*3+2];
        float D = sqrtf(dx*dx + dy*dy + dz*dz + 1e-6f);
        rbf16(D, &rbfs[t*16], 1);
    }
    __syncthreads();
    int lane = t & 31, w = t >> 5;
    float4 bye4 = ((const float4*)b_ye)[lane];
    float4 g4   = ((const float4*)g_ye)[lane];
    float4 be4  = ((const float4*)bn_ye)[lane];
    float4* o4 = (float4*)out;
    size_t yebase4 = YE_OFF >> 2;
    for (int u = w; u < 136; u += 8) {
        float4 a = bye4;
#pragma unroll
        for (int r = 0; r < 16; r++) {
            float rb = rbfs[u*16 + r];
            float4 wv = ((const float4*)&WyeS[r*128])[lane];
            a.x = fmaf(rb, wv.x, a.x); a.y = fmaf(rb, wv.y, a.y);
            a.z = fmaf(rb, wv.z, a.z); a.w = fmaf(rb, wv.w, a.w);
        }
        float4 res = ln128(a, g4, be4);
        int m1 = sm1[u], m2 = sm2[u];
        size_t r1 = (size_t)bl*256 + m1*16 + m2;
        size_t r2 = (size_t)bl*256 + m2*16 + m1;
        o4[yebase4 + r1*32 + lane] = res;
        if (r2 != r1) o4[yebase4 + r2*32 + lane] = res;
    }
}

// ---------------- launch: multi-stream DAG inside graph capture ----------------
extern "C" void kernel_launch(void* const* d_in, const int* in_sizes, int n_in,
                              void* d_out, int out_size) {
    const float* X        = (const float*)d_in[0];
    const float* Y        = (const float*)d_in[1];
    const float* Y_m      = (const float*)d_in[2];
    const float* mask     = (const float*)d_in[3];
    const float* W_pos    = (const float*)d_in[4];
    const float* b_pos    = (const float*)d_in[5];
    const float* W_edge   = (const float*)d_in[6];
    const float* b_edge   = (const float*)d_in[7];
    const float* g_edge   = (const float*)d_in[8];
    const float* be_edge  = (const float*)d_in[9];
    const float* W_down   = (const float*)d_in[10];
    const float* b_down   = (const float*)d_in[11];
    const float* g_node   = (const float*)d_in[12];
    const float* bn_node  = (const float*)d_in[13];
    const float* W_type   = (const float*)d_in[14];
    const float* b_type   = (const float*)d_in[15];
    const float* W_yn     = (const float*)d_in[16];
    const float* b_yn     = (const float*)d_in[17];
    const float* g_yn     = (const float*)d_in[18];
    const float* bn_yn    = (const float*)d_in[19];
    const float* W_ye     = (const float*)d_in[20];
    const float* b_ye     = (const float*)d_in[21];
    const float* g_ye     = (const float*)d_in[22];
    const float* bn_ye    = (const float*)d_in[23];
    const int*   Y_t      = (const int*)d_in[24];
    const int*   R_idx    = (const int*)d_in[25];
    const int*   chains   = (const int*)d_in[26];
    const int*   pt       = (const int*)d_in[27];
    float* out = (float*)d_out;

    static bool init_done = false;
    static cudaStream_t s2, s3;
    static cudaEvent_t evRoot, evAtoms, evTF, evS2, evS3;
    if (!init_done) {
        cudaStreamCreateWithFlags(&s2, cudaStreamNonBlocking);
        cudaStreamCreateWithFlags(&s3, cudaStreamNonBlocking);
        cudaEventCreateWithFlags(&evRoot,  cudaEventDisableTiming);
        cudaEventCreateWithFlags(&evAtoms, cudaEventDisableTiming);
        cudaEventCreateWithFlags(&evTF,    cudaEventDisableTiming);
        cudaEventCreateWithFlags(&evS2,    cudaEventDisableTiming);
        cudaEventCreateWithFlags(&evS3,    cudaEventDisableTiming);
        cudaFuncSetAttribute(k_edge,  cudaFuncAttributeMaxDynamicSharedMemorySize, EDGE_SMF*4);
        cudaFuncSetAttribute(k_vnode, cudaFuncAttributeMaxDynamicSharedMemorySize, VN_SMF*4);
        init_done = true;
    }

    // fork from origin stream
    cudaEventRecord(evRoot, 0);
    cudaStreamWaitEvent(s2, evRoot, 0);
    cudaStreamWaitEvent(s3, evRoot, 0);

    // s3: yedge (independent of everything precomputed)
    k_yedge<<<BB*LLEN, 256, 0, s3>>>(Y, W_ye, b_ye, g_ye, bn_ye, out);
    cudaEventRecord(evS3, s3);

    // s2: weight prep chain
    k_trans<<<(416*128 + 148*128 + 96*128 + 147*128 + 255)/256, 256, 0, s2>>>(W_edge, W_down, W_yn);
    k_fuse<<<(66*128 + 147*128 + 128 + 255)/256, 256, 0, s2>>>(W_pos, b_pos, W_edge, W_type, b_type, b_down);
    cudaEventRecord(evTF, s2);
    k_ynode<<<NROW/8, 256, 0, s2>>>(Y_m, Y_t, pt, b_yn, g_yn, bn_yn, out);

    // s0: geometry chain
    k_atoms<<<NRES/256, 256>>>(X);
    cudaEventRecord(evAtoms, 0);

    // s2: vnode needs atoms + trans + fuse
    cudaStreamWaitEvent(s2, evAtoms, 0);
    k_vnode<<<NROW/64, 256, VN_SMF*4, s2>>>(Y, Y_t, pt, g_node, bn_node, out);
    cudaEventRecord(evS2, s2);

    // s0: topk then edge (edge also needs trans+fuse)
    k_topk<<<NRES, 256, 0, 0>>>(mask, out);
    cudaStreamWaitEvent(0, evTF, 0);
    k_edge<<<NEDGE/64, 256, EDGE_SMF*4, 0>>>(R_idx, chains, b_edge, g_edge, be_edge, out);

    // join
    cudaStreamWaitEvent(0, evS2, 0);
    cudaStreamWaitEvent(0, evS3, 0);
}

// round 13
// speedup vs baseline: 1.4656x; 1.4656x over previous
#include <cuda_runtime.h>
#include <cuda_bf16.h>

#define BB 2
#define LLEN 2048
#define MM 16
#define KNN 32
#define NRES (BB*LLEN)            // 4096
#define NEDGE (NRES*KNN)          // 131072
#define NROW (NRES*MM)            // 65536

static const size_t V_OFF  = 0;
static const size_t E_OFF  = (size_t)NROW*128;                  // 8388608
static const size_t EI_OFF = E_OFF + (size_t)NEDGE*128;         // 25165824
static const size_t YN_OFF = EI_OFF + (size_t)NEDGE;            // 25296896
static const size_t YE_OFF = YN_OFF + (size_t)NROW*128;         // 33685504
static const size_t YM_OFF = YE_OFF + (size_t)NRES*MM*MM*128;   // 167903232

typedef unsigned long long ull;

// ---------------- device scratch ----------------
__device__ float g_atoms[NRES*15];
__device__ float g_cax[NRES*3];
__device__ int   g_eidx[NEDGE];
__device__ float g_dnb[NEDGE];
__device__ float g_WeT[416*128];      // W_edge^T [f][n]
__device__ float g_WdTF[148*128];     // W_down^T full [f][n]
__device__ float g_WdT2[96*128];      // compact rows
__device__ float g_WynT[147*128];     // W_yn^T [f][c]
__device__ float g_Tpos[66*128];      // fused pos table
__device__ float g_Wfuse[147*128];    // Wt^T . Wd[:,80:144]^T
__device__ float g_btf[128];          // fused bias

// pairs (excluding leading D_neighbors block); atoms: N=0,Ca=1,C=2,O=3,Cb=4
__constant__ int c_PA24[24] = {0,2,3,4, 1,1,1,1, 0,0,0, 4,4, 3, 0,2,3,4, 2,3,4, 2,3, 2};
__constant__ int c_PB24[24] = {0,2,3,4, 0,2,3,4, 2,3,4, 2,3, 2, 1,1,1,1, 0,0,0, 4,4, 3};

// ---------------- f32x2 helpers ----------------
__device__ __forceinline__ ull pack2(float s) {
    ull r; asm("mov.b64 %0, {%1, %1};" : "=l"(r) : "r"(__float_as_uint(s))); return r;
}
__device__ __forceinline__ void ffma2(ull& a, ull s, ull w) {
    asm("fma.rn.f32x2 %0, %1, %2, %0;" : "+l"(a) : "l"(s), "l"(w));
}
__device__ __forceinline__ float2 unpack2(ull a) {
    unsigned lo, hi; asm("mov.b64 {%0, %1}, %2;" : "=r"(lo), "=r"(hi) : "l"(a));
    return make_float2(__uint_as_float(lo), __uint_as_float(hi));
}
__device__ __forceinline__ float4 ln128(float4 a, float4 g, float4 be) {
    float s  = a.x + a.y + a.z + a.w;
    float ss = fmaf(a.x,a.x, fmaf(a.y,a.y, fmaf(a.z,a.z, a.w*a.w)));
#pragma unroll
    for (int o = 16; o; o >>= 1) {
        s  += __shfl_xor_sync(0xffffffffu, s,  o);
        ss += __shfl_xor_sync(0xffffffffu, ss, o);
    }
    float mu   = s * 0.0078125f;
    float var  = ss * 0.0078125f - mu*mu;
    float rstd = rsqrtf(var + 1e-5f);
    float4 o4;
    o4.x = (a.x-mu)*rstd*g.x + be.x;
    o4.y = (a.y-mu)*rstd*g.y + be.y;
    o4.z = (a.z-mu)*rstd*g.z + be.z;
    o4.w = (a.w-mu)*rstd*g.w + be.w;
    return o4;
}

// 16 RBF values with 4 exps: anchor at nearest mu, geometric ratio chain.
__device__ __forceinline__ void rbf16(float D, float* dst, int stride) {
    const float DLT = 1.3333333333333333f;
    const float IS2 = 0.64f;
    const float C1  = 1.7066666666666668f;
    const float C2  = 1.1377777777777778f;
    float u = (D - 2.0f) * 0.75f;
    int rs = __float2int_rn(u);
    rs = rs < 0 ? 0 : (rs > 15 ? 15 : rs);
    float x = D - (2.0f + DLT * (float)rs);
    float peak  = __expf(-x*x*IS2);
    float fup   = __expf( C1*x - C2);
    float fdn   = __expf(-C1*x - C2);
    float decay = __expf(-2.0f*C2);
    float v = peak;
    dst[rs*stride] = v;
    float f = fup;
    for (int r = rs+1; r < 16; r++) { v *= f; dst[r*stride] = v; f *= decay; }
    v = peak; f = fdn;
    for (int r = rs-1; r >= 0; r--) { v *= f; dst[r*stride] = v; f *= decay; }
}

// ---------------- prep kernels ----------------
__global__ void k_atoms(const float* __restrict__ X) {
    int r = blockIdx.x*blockDim.x + threadIdx.x;
    if (r >= NRES) return;
    const float* x = X + (size_t)r*12;
    float nx=x[0],ny=x[1],nz=x[2], cax=x[3],cay=x[4],caz=x[5];
    float cxx=x[6],cyy=x[7],czz=x[8], ox=x[9],oy=x[10],oz=x[11];
    float bx=cax-nx, by=cay-ny, bz=caz-nz;
    float ccx=cxx-cax, ccy=cyy-cay, ccz=czz-caz;
    float ax=by*ccz-bz*ccy, ay=bz*ccx-bx*ccz, az=bx*ccy-by*ccx;
    float cbx=-0.58273431f*ax+0.56802827f*bx-0.54067466f*ccx+cax;
    float cby=-0.58273431f*ay+0.56802827f*by-0.54067466f*ccy+cay;
    float cbz=-0.58273431f*az+0.56802827f*bz-0.54067466f*ccz+caz;
    float* o = g_atoms + (size_t)r*15;
    o[0]=nx;o[1]=ny;o[2]=nz; o[3]=cax;o[4]=cay;o[5]=caz;
    o[6]=cxx;o[7]=cyy;o[8]=czz; o[9]=ox;o[10]=oy;o[11]=oz;
    o[12]=cbx;o[13]=cby;o[14]=cbz;
    g_cax[r*3+0]=cax; g_cax[r*3+1]=cay; g_cax[r*3+2]=caz;
}

__global__ void k_trans(const float* __restrict__ We, const float* __restrict__ Wd,
                        const float* __restrict__ Wyn) {
    int i = blockIdx.x*blockDim.x + threadIdx.x;
    if (i < 416*128) { int f=i>>7, n=i&127; g_WeT[i] = We[n*416+f]; return; }
    i -= 416*128;
    if (i < 148*128) { int f=i>>7, n=i&127; g_WdTF[i] = Wd[n*148+f]; return; }
    i -= 148*128;
    if (i < 96*128) {
        int f=i>>7, n=i&127;
        float v = 0.0f;
        if (f < 80) v = Wd[n*148+f];
        else if (f < 84) v = Wd[n*148+144+(f-80)];
        g_WdT2[i] = v; return;
    }
    i -= 96*128;
    if (i < 147*128) { int f=i>>7, c=i&127; g_WynT[i] = Wyn[c*147+f]; }
}

__global__ void k_fuse(const float* __restrict__ Wp, const float* __restrict__ bp,
                       const float* __restrict__ We, const float* __restrict__ Wt,
                       const float* __restrict__ bt, const float* __restrict__ bd) {
    int i = blockIdx.x*blockDim.x + threadIdx.x;
    if (i < 66*128) {
        int d = i>>7, n = i&127;
        float s = 0.0f;
        for (int c = 0; c < 16; c++) s = fmaf(Wp[c*66+d] + bp[c], We[n*416+c], s);
        g_Tpos[i] = s; return;
    }
    i -= 66*128;
    if (i < 147*128) {
        int f = i>>7, n = i&127;
        float s = 0.0f;
        for (int c = 0; c < 64; c++) s = fmaf(Wt[c*147+f], g_WdTF[(80+c)*128+n], s);
        g_Wfuse[i] = s; return;
    }
    i -= 147*128;
    if (i < 128) {
        float s = bd[i];
        for (int c = 0; c < 64; c++) s = fmaf(bt[c], g_WdTF[(80+c)*128+i], s);
        g_btf[i] = s;
    }
}

// ---------------- top-K neighbors: histogram pre-filter + exact warp selection ----------------
__global__ __launch_bounds__(256) void k_topk(const float* __restrict__ mask,
                                              float* __restrict__ out) {
    int row = blockIdx.x, b = row >> 11, t = threadIdx.x;
    int lane = t & 31, w = t >> 5;
    __shared__ float smax[8];
    __shared__ unsigned hist[256];
    __shared__ float pd[2048];
    __shared__ int   pj[2048];
    __shared__ int   scnt;
    __shared__ int   sthr;

    hist[t] = 0u;
    if (t == 0) scnt = 0;

    float cx = g_cax[row*3], cy = g_cax[row*3+1], cz = g_cax[row*3+2];
    float mi = mask[row];
    float dv[8], m2v[8];
    float lmax = -1e30f;
#pragma unroll
    for (int q = 0; q < 8; q++) {
        int jr = b*LLEN + t + (q<<8);
        float dx = cx - g_cax[jr*3], dy = cy - g_cax[jr*3+1], dz = cz - g_cax[jr*3+2];
        float dist = sqrtf(dx*dx + dy*dy + dz*dz + 1e-6f);
        float m2 = mi * mask[jr];
        dv[q] = m2 * dist; m2v[q] = m2;
        lmax = fmaxf(lmax, dv[q]);
    }
#pragma unroll
    for (int o = 16; o; o >>= 1) lmax = fmaxf(lmax, __shfl_xor_sync(0xffffffffu, lmax, o));
    if (lane == 0) smax[w] = lmax;
    __syncthreads();
    float dmax = fmaxf(fmaxf(fmaxf(smax[0],smax[1]),fmaxf(smax[2],smax[3])),
                       fmaxf(fmaxf(smax[4],smax[5]),fmaxf(smax[6],smax[7])));
    float inv = 256.0f / (dmax + 1e-6f);
#pragma unroll
    for (int q = 0; q < 8; q++) {
        dv[q] += (1.0f - m2v[q]) * dmax;
        int bq = (int)(dv[q] * inv);
        bq = bq < 0 ? 0 : (bq > 255 ? 255 : bq);
        atomicAdd(&hist[bq], 1u);
    }
    __syncthreads();

    if (w == 0) {
        unsigned s = 0;
#pragma unroll
        for (int k = 0; k < 8; k++) s += hist[lane*8 + k];
        unsigned scan = s;
#pragma unroll
        for (int o = 1; o < 32; o <<= 1) {
            unsigned v = __shfl_up_sync(0xffffffffu, scan, o);
            if (lane >= o) scan += v;
        }
        unsigned ballot = __ballot_sync(0xffffffffu, scan >= KNN);
        int fl = __ffs(ballot) - 1;
        if (lane == fl) {
            unsigned cum = scan - s;
            int bt_ = lane*8;
            for (int k = 0; k < 8; k++) {
                cum += hist[lane*8 + k];
                if (cum >= KNN) { bt_ = lane*8 + k; break; }
            }
            sthr = bt_;
        }
    }
    __syncthreads();

    int thr = sthr;
#pragma unroll
    for (int q = 0; q < 8; q++) {
        int bq = (int)(dv[q] * inv);
        bq = bq < 0 ? 0 : (bq > 255 ? 255 : bq);
        if (bq <= thr) {
            int p = atomicAdd(&scnt, 1);
            pd[p] = dv[q];
            pj[p] = t + (q<<8);
        }
    }
    __syncthreads();

    if (w == 0) {
        int n = scnt;
        for (int it = 0; it < KNN; it++) {
            float bv = 3e38f; int bj = 0x7fffffff; int bp = -1;
            for (int i = lane; i < n; i += 32) {
                float v = pd[i]; int j = pj[i];
                if (v < bv || (v == bv && j < bj)) { bv = v; bj = j; bp = i; }
            }
            float rv = bv; int rj = bj;
#pragma unroll
            for (int o = 16; o; o >>= 1) {
                float ov = __shfl_xor_sync(0xffffffffu, rv, o);
                int   oj = __shfl_xor_sync(0xffffffffu, rj, o);
                if (ov < rv || (ov == rv && oj < rj)) { rv = ov; rj = oj; }
            }
            if (bp >= 0 && rv == bv && rj == bj) pd[bp] = 3e38f;
            if (lane == 0) {
                g_eidx[(size_t)row*KNN + it] = rj;
                g_dnb [(size_t)row*KNN + it] = rv;
                out[EI_OFF + (size_t)row*KNN + it] = (float)rj;
            }
            __syncwarp();
        }
    }
}

// ---------------- Edge: features + GEMM(400->128, W via L1/L2) + Tpos + LN ----------------
#define EFEAT_ROWS 144
#define EDGE_SMF (EFEAT_ROWS*64 + 32 + 960 + 64 + 64 + 64)   // 10400 floats = 41.6KB
__global__ __launch_bounds__(256, 3) void k_edge(
    const int* __restrict__ R_idx, const int* __restrict__ chains,
    const float* __restrict__ b_edge, const float* __restrict__ g_edge,
    const float* __restrict__ be_edge, float* __restrict__ out) {
    extern __shared__ float sm[];
    float* feats = sm;                       // [144][64]
    float* ai    = sm + EFEAT_ROWS*64;       // 32
    float* aj    = ai + 32;                  // [64][15]
    float* dnb   = aj + 960;                 // 64
    int*   sJ    = (int*)(dnb + 64);         // 64
    int*   sdc   = sJ + 64;                  // 64

    int t = threadIdx.x;
    int r0 = blockIdx.x * 2;
    int b  = r0 >> 11;
    int ebase = blockIdx.x * 64;
    int lane = t & 31, w = t >> 5;

    if (t < 30) ai[t] = g_atoms[r0*15 + t];
    if (t < 64) { sJ[t] = g_eidx[ebase + t]; dnb[t] = g_dnb[ebase + t]; }
    __syncthreads();
    for (int k = t; k < 960; k += 256) {
        int e = k / 15, c = k % 15;
        aj[k] = g_atoms[(size_t)(b*LLEN + sJ[e])*15 + c];
    }
    if (t < 64) {
        int ig = r0 + (t >> 5);
        int jg = b*LLEN + sJ[t];
        int off = R_idx[ig] - R_idx[jg];
        int ec  = (chains[ig] == chains[jg]);
        int d = off + 32; d = d < 0 ? 0 : (d > 64 ? 64 : d);
        sdc[t] = ec ? d : 65;
    }
    __syncthreads();

    ull acc[16];
    {
        float4 b4 = ((const float4*)b_edge)[lane];
        ull b0 = pack2(b4.x), b1 = pack2(b4.y), b2 = pack2(b4.z), b3 = pack2(b4.w);
#pragma unroll
        for (int p = 0; p < 4; p++) { acc[p*4]=b0; acc[p*4+1]=b1; acc[p*4+2]=b2; acc[p*4+3]=b3; }
    }

    int pbase = 0;
    for (int ph = 0; ph < 3; ph++) {
        int P = ph ? 8 : 9;
        {
            int e = t & 63, psub = t >> 6;
            const float* A  = ai + (e >> 5) * 15;
            const float* Bv = aj + e * 15;
            for (int p = psub; p < P; p += 4) {
                int gp = pbase + p;
                float D;
                if (gp == 0) D = dnb[e];
                else {
                    int pa = c_PA24[gp-1]*3, pb = c_PB24[gp-1]*3;
                    float dx=A[pa]-Bv[pb], dy=A[pa+1]-Bv[pb+1], dz=A[pa+2]-Bv[pb+2];
                    D = sqrtf(dx*dx + dy*dy + dz*dz + 1e-6f);
                }
                rbf16(D, &feats[(p*16)*64 + e], 64);
            }
        }
        __syncthreads();                 // feats ready for this phase
        for (int kc = 0; kc < P; kc++) {
            const float4* Wg = (const float4*)g_WeT + (size_t)(pbase+kc+1)*512 + lane;
            const float* fb = feats + (kc*16)*64 + 8*w;
#pragma unroll
            for (int fi = 0; fi < 16; fi++) {
                float4 w4 = __ldg(&Wg[fi*32]);
                ulonglong2 f01 = *(const ulonglong2*)&fb[fi*64];
                ulonglong2 f23 = *(const ulonglong2*)&fb[fi*64 + 4];
                ull w0 = pack2(w4.x), w1 = pack2(w4.y), w2 = pack2(w4.z), w3 = pack2(w4.w);
                ffma2(acc[0],  f01.x, w0); ffma2(acc[1],  f01.x, w1);
                ffma2(acc[2],  f01.x, w2); ffma2(acc[3],  f01.x, w3);
                ffma2(acc[4],  f01.y, w0); ffma2(acc[5],  f01.y, w1);
                ffma2(acc[6],  f01.y, w2); ffma2(acc[7],  f01.y, w3);
                ffma2(acc[8],  f23.x, w0); ffma2(acc[9],  f23.x, w1);
                ffma2(acc[10], f23.x, w2); ffma2(acc[11], f23.x, w3);
                ffma2(acc[12], f23.y, w0); ffma2(acc[13], f23.y, w1);
                ffma2(acc[14], f23.y, w2); ffma2(acc[15], f23.y, w3);
            }
        }
        __syncthreads();                 // protect feats before next phase writes
        pbase += P;
    }

    float4 g4  = ((const float4*)g_edge)[lane];
    float4 be4 = ((const float4*)be_edge)[lane];
    float4* o4 = (float4*)(out + E_OFF);
#pragma unroll
    for (int p = 0; p < 4; p++) {
        float2 u0 = unpack2(acc[p*4]);
        float2 u1 = unpack2(acc[p*4+1]);
        float2 u2 = unpack2(acc[p*4+2]);
        float2 u3 = unpack2(acc[p*4+3]);
        int e0 = 8*w + 2*p, e1 = e0 + 1;
        float4 tp0 = ((const float4*)g_Tpos)[sdc[e0]*32 + lane];
        float4 tp1 = ((const float4*)g_Tpos)[sdc[e1]*32 + lane];
        float4 a0 = make_float4(u0.x+tp0.x, u1.x+tp0.y, u2.x+tp0.z, u3.x+tp0.w);
        float4 a1 = make_float4(u0.y+tp1.x, u1.y+tp1.y, u2.y+tp1.z, u3.y+tp1.w);
        float4 r0v = ln128(a0, g4, be4);
        float4 r1v = ln128(a1, g4, be4);
        o4[(size_t)(ebase+e0)*32 + lane] = r0v;
        o4[(size_t)(ebase+e1)*32 + lane] = r1v;
    }
}

// ---------------- V node: features + GEMM(96->128, W via L1/L2) + fuse + LN ----------------
#define VN_SMF (96*64 + 64 + 192 + 36 + 192)   // 6628 floats = 26.5KB
__global__ __launch_bounds__(256, 3) void k_vnode(
    const float* __restrict__ Y, const int* __restrict__ Y_t, const int* __restrict__ pt,
    const float* __restrict__ g_node, const float* __restrict__ bn_node,
    float* __restrict__ out) {
    extern __shared__ float sm[];
    float* feats = sm;                    // [96][64]
    float* at    = sm + 96*64;            // [4][15] pad 64
    float* ys    = at + 64;               // [64][3]
    float* fr    = ys + 192;              // [4][9]
    int*   cols  = (int*)(fr + 36);       // [64][3]

    int t = threadIdx.x;
    int bid = blockIdx.x;
    int rbase = bid * 4;
    int rowg0 = bid * 64;
    int lane = t & 31, w = t >> 5;

    if (t < 60) at[t] = g_atoms[(size_t)rbase*15 + t];
    if (t < 192) ys[t] = Y[(size_t)rowg0*3 + t];
    if (t < 64) {
        int yt = Y_t[rowg0 + t];
        cols[t*3+0] = yt;
        cols[t*3+1] = 120 + pt[120 + yt];
        cols[t*3+2] = 139 + pt[240 + yt];
    }
    for (int idx = t; idx < 12*64; idx += 256) feats[84*64 + idx] = 0.0f;
    __syncthreads();
    if (t < 4) {
        const float* A = at + t*15;
        float v1x=A[0]-A[3], v1y=A[1]-A[4], v1z=A[2]-A[5];
        float v2x=A[6]-A[3], v2y=A[7]-A[4], v2z=A[8]-A[5];
        float n1 = sqrtf(v1x*v1x+v1y*v1y+v1z*v1z) + 1e-8f;
        float e1x=v1x/n1, e1y=v1y/n1, e1z=v1z/n1;
        float d12 = e1x*v2x + e1y*v2y + e1z*v2z;
        float ux=v2x-e1x*d12, uy=v2y-e1y*d12, uz=v2z-e1z*d12;
        float n2 = sqrtf(ux*ux+uy*uy+uz*uz) + 1e-8f;
        float e2x=ux/n2, e2y=uy/n2, e2z=uz/n2;
        float e3x=e1y*e2z-e1z*e2y, e3y=e1z*e2x-e1x*e2z, e3z=e1x*e2y-e1y*e2x;
        float* F = fr + t*9;
        F[0]=e1x;F[1]=e1y;F[2]=e1z; F[3]=e2x;F[4]=e2y;F[5]=e2z; F[6]=e3x;F[7]=e3y;F[8]=e3z;
    }
    {
        int row = t & 63, res = row >> 4;
        const float* yy = ys + row*3;
        for (int p = t >> 6; p < 5; p += 4) {
            const float* A = at + res*15 + p*3;
            float dx=A[0]-yy[0], dy=A[1]-yy[1], dz=A[2]-yy[2];
            float D = sqrtf(dx*dx+dy*dy+dz*dz + 1e-6f);
            rbf16(D, &feats[(p*16)*64 + row], 64);
        }
    }
    __syncthreads();
    if (t < 64) {
        int row = t, res = row >> 4;
        const float* F = fr + res*9;
        float dx = ys[row*3]   - at[res*15+3];
        float dy = ys[row*3+1] - at[res*15+4];
        float dz = ys[row*3+2] - at[res*15+5];
        float lv0 = F[0]*dx+F[1]*dy+F[2]*dz;
        float lv1 = F[3]*dx+F[4]*dy+F[5]*dz;
        float lv2 = F[6]*dx+F[7]*dy+F[8]*dz;
        float rxy  = sqrtf(lv0*lv0 + lv1*lv1 + 1e-8f);
        float rxyz = sqrtf(lv0*lv0 + lv1*lv1 + lv2*lv2) + 1e-8f;
        feats[80*64+row] = lv0/rxy;
        feats[81*64+row] = lv1/rxy;
        feats[82*64+row] = rxy/rxyz;
        feats[83*64+row] = lv2/rxyz;
    }
    __syncthreads();
    ull acc[16];
    {
        float4 b4 = ((const float4*)g_btf)[lane];
        ull b0 = pack2(b4.x), b1 = pack2(b4.y), b2 = pack2(b4.z), b3 = pack2(b4.w);
#pragma unroll
        for (int p = 0; p < 4; p++) { acc[p*4]=b0; acc[p*4+1]=b1; acc[p*4+2]=b2; acc[p*4+3]=b3; }
    }
    for (int kc = 0; kc < 6; kc++) {
        const float4* Wg = (const float4*)g_WdT2 + (size_t)kc*512 + lane;
        const float* fb = feats + (kc*16)*64 + 8*w;
#pragma unroll
        for (int fi = 0; fi < 16; fi++) {
            float4 w4 = __ldg(&Wg[fi*32]);
            ulonglong2 f01 = *(const ulonglong2*)&fb[fi*64];
            ulonglong2 f23 = *(const ulonglong2*)&fb[fi*64 + 4];
            ull w0 = pack2(w4.x), w1 = pack2(w4.y), w2 = pack2(w4.z), w3 = pack2(w4.w);
            ffma2(acc[0],  f01.x, w0); ffma2(acc[1],  f01.x, w1);
            ffma2(acc[2],  f01.x, w2); ffma2(acc[3],  f01.x, w3);
            ffma2(acc[4],  f01.y, w0); ffma2(acc[5],  f01.y, w1);
            ffma2(acc[6],  f01.y, w2); ffma2(acc[7],  f01.y, w3);
            ffma2(acc[8],  f23.x, w0); ffma2(acc[9],  f23.x, w1);
            ffma2(acc[10], f23.x, w2); ffma2(acc[11], f23.x, w3);
            ffma2(acc[12], f23.y, w0); ffma2(acc[13], f23.y, w1);
            ffma2(acc[14], f23.y, w2); ffma2(acc[15], f23.y, w3);
        }
    }
    float4 g4  = ((const float4*)g_node)[lane];
    float4 be4 = ((const float4*)bn_node)[lane];
    float4* o4 = (float4*)(out + V_OFF);
#pragma unroll
    for (int p = 0; p < 4; p++) {
        float2 u0 = unpack2(acc[p*4]);
        float2 u1 = unpack2(acc[p*4+1]);
        float2 u2 = unpack2(acc[p*4+2]);
        float2 u3 = unpack2(acc[p*4+3]);
        int e0 = 8*w + 2*p, e1 = e0 + 1;
        float4 a0 = make_float4(u0.x, u1.x, u2.x, u3.x);
        float4 a1 = make_float4(u0.y, u1.y, u2.y, u3.y);
#pragma unroll
        for (int j = 0; j < 3; j++) {
            float4 q0 = ((const float4*)g_Wfuse)[cols[e0*3+j]*32 + lane];
            float4 q1 = ((const float4*)g_Wfuse)[cols[e1*3+j]*32 + lane];
            a0.x+=q0.x; a0.y+=q0.y; a0.z+=q0.z; a0.w+=q0.w;
            a1.x+=q1.x; a1.y+=q1.y; a1.z+=q1.z; a1.w+=q1.w;
        }
        float4 r0v = ln128(a0, g4, be4);
        float4 r1v = ln128(a1, g4, be4);
        o4[(size_t)(rowg0+e0)*32 + lane] = r0v;
        o4[(size_t)(rowg0+e1)*32 + lane] = r1v;
    }
}

// ---------------- Y_nodes (gather + LN) + Y_m copy ----------------
__global__ __launch_bounds__(256) void k_ynode(
    const float* __restrict__ Y_m, const int* __restrict__ Y_t, const int* __restrict__ pt,
    const float* __restrict__ b_yn, const float* __restrict__ g_yn,
    const float* __restrict__ bn_yn, float* __restrict__ out) {
    int t = threadIdx.x, lane = t & 31, w = t >> 5;
    int row = blockIdx.x*8 + w;
    int yt = Y_t[row];
    int c0 = yt, c1 = 120 + pt[120+yt], c2 = 139 + pt[240+yt];
    float4 a  = ((const float4*)&g_WynT[(size_t)c0*128])[lane];
    float4 a1 = ((const float4*)&g_WynT[(size_t)c1*128])[lane];
    float4 a2 = ((const float4*)&g_WynT[(size_t)c2*128])[lane];
    float4 b4 = ((const float4*)b_yn)[lane];
    a.x += a1.x + a2.x + b4.x;
    a.y += a1.y + a2.y + b4.y;
    a.z += a1.z + a2.z + b4.z;
    a.w += a1.w + a2.w + b4.w;
    float4 g4  = ((const float4*)g_yn)[lane];
    float4 be4 = ((const float4*)bn_yn)[lane];
    float4 r = ln128(a, g4, be4);
    ((float4*)(out + YN_OFF))[(size_t)row*32 + lane] = r;
    if (lane == 0) out[YM_OFF + row] = Y_m[row];
}

// ---------------- Y_edges: symmetric pairs, 16->128 + LN ----------------
__global__ __launch_bounds__(256) void k_yedge(
    const float* __restrict__ Y, const float* __restrict__ W_ye,
    const float* __restrict__ b_ye, const float* __restrict__ g_ye,
    const float* __restrict__ bn_ye, float* __restrict__ out) {
    __shared__ float ys[48];
    __shared__ float rbfs[136*16];
    __shared__ float WyeS[16*128];
    __shared__ int sm1[136], sm2[136];
    int t = threadIdx.x, bl = blockIdx.x;
    if (t < 48) ys[t] = Y[(size_t)bl*48 + t];
    for (int i = t; i < 2048; i += 256) {
        int c = i >> 4, r = i & 15;
        WyeS[r*128 + c] = W_ye[i];
    }
    if (t < 136) {
        int u = t, m1 = 0;
        while (u >= 16 - m1) { u -= 16 - m1; m1++; }
        sm1[t] = m1; sm2[t] = m1 + u;
    }
    __syncthreads();
    if (t < 136) {
        int m1 = sm1[t], m2 = sm2[t];
        float dx = ys[m1*3]-ys[m2*3], dy = ys[m1*3+1]-ys[m2*3+1], dz = ys[m1*3+2]-ys[m2*3+2];
        float D = sqrtf(dx*dx + dy*dy + dz*dz + 1e-6f);
        rbf16(D, &rbfs[t*16], 1);
    }
    __syncthreads();
    int lane = t & 31, w = t >> 5;
    float4 bye4 = ((const float4*)b_ye)[lane];
    float4 g4   = ((const float4*)g_ye)[lane];
    float4 be4  = ((const float4*)bn_ye)[lane];
    float4* o4 = (float4*)out;
    size_t yebase4 = YE_OFF >> 2;
    for (int u = w; u < 136; u += 8) {
        float4 a = bye4;
#pragma unroll
        for (int r = 0; r < 16; r++) {
            float rb = rbfs[u*16 + r];
            float4 wv = ((const float4*)&WyeS[r*128])[lane];
            a.x = fmaf(rb, wv.x, a.x); a.y = fmaf(rb, wv.y, a.y);
            a.z = fmaf(rb, wv.z, a.z); a.w = fmaf(rb, wv.w, a.w);
        }
        float4 res = ln128(a, g4, be4);
        int m1 = sm1[u], m2 = sm2[u];
        size_t r1 = (size_t)bl*256 + m1*16 + m2;
        size_t r2 = (size_t)bl*256 + m2*16 + m1;
        o4[yebase4 + r1*32 + lane] = res;
        if (r2 != r1) o4[yebase4 + r2*32 + lane] = res;
    }
}

// ---------------- launch: multi-stream DAG inside graph capture ----------------
extern "C" void kernel_launch(void* const* d_in, const int* in_sizes, int n_in,
                              void* d_out, int out_size) {
    const float* X        = (const float*)d_in[0];
    const float* Y        = (const float*)d_in[1];
    const float* Y_m      = (const float*)d_in[2];
    const float* mask     = (const float*)d_in[3];
    const float* W_pos    = (const float*)d_in[4];
    const float* b_pos    = (const float*)d_in[5];
    const float* W_edge   = (const float*)d_in[6];
    const float* b_edge   = (const float*)d_in[7];
    const float* g_edge   = (const float*)d_in[8];
    const float* be_edge  = (const float*)d_in[9];
    const float* W_down   = (const float*)d_in[10];
    const float* b_down   = (const float*)d_in[11];
    const float* g_node   = (const float*)d_in[12];
    const float* bn_node  = (const float*)d_in[13];
    const float* W_type   = (const float*)d_in[14];
    const float* b_type   = (const float*)d_in[15];
    const float* W_yn     = (const float*)d_in[16];
    const float* b_yn     = (const float*)d_in[17];
    const float* g_yn     = (const float*)d_in[18];
    const float* bn_yn    = (const float*)d_in[19];
    const float* W_ye     = (const float*)d_in[20];
    const float* b_ye     = (const float*)d_in[21];
    const float* g_ye     = (const float*)d_in[22];
    const float* bn_ye    = (const float*)d_in[23];
    const int*   Y_t      = (const int*)d_in[24];
    const int*   R_idx    = (const int*)d_in[25];
    const int*   chains   = (const int*)d_in[26];
    const int*   pt       = (const int*)d_in[27];
    float* out = (float*)d_out;

    static bool init_done = false;
    static cudaStream_t s2, s3;
    static cudaEvent_t evRoot, evAtoms, evTF, evS2, evS3;
    if (!init_done) {
        cudaStreamCreateWithFlags(&s2, cudaStreamNonBlocking);
        cudaStreamCreateWithFlags(&s3, cudaStreamNonBlocking);
        cudaEventCreateWithFlags(&evRoot,  cudaEventDisableTiming);
        cudaEventCreateWithFlags(&evAtoms, cudaEventDisableTiming);
        cudaEventCreateWithFlags(&evTF,    cudaEventDisableTiming);
        cudaEventCreateWithFlags(&evS2,    cudaEventDisableTiming);
        cudaEventCreateWithFlags(&evS3,    cudaEventDisableTiming);
        cudaFuncSetAttribute(k_edge,  cudaFuncAttributeMaxDynamicSharedMemorySize, EDGE_SMF*4);
        cudaFuncSetAttribute(k_vnode, cudaFuncAttributeMaxDynamicSharedMemorySize, VN_SMF*4);
        init_done = true;
    }

    // fork from origin stream
    cudaEventRecord(evRoot, 0);
    cudaStreamWaitEvent(s2, evRoot, 0);
    cudaStreamWaitEvent(s3, evRoot, 0);

    // s3: yedge (independent of everything precomputed)
    k_yedge<<<BB*LLEN, 256, 0, s3>>>(Y, W_ye, b_ye, g_ye, bn_ye, out);
    cudaEventRecord(evS3, s3);

    // s2: weight prep chain
    k_trans<<<(416*128 + 148*128 + 96*128 + 147*128 + 255)/256, 256, 0, s2>>>(W_edge, W_down, W_yn);
    k_fuse<<<(66*128 + 147*128 + 128 + 255)/256, 256, 0, s2>>>(W_pos, b_pos, W_edge, W_type, b_type, b_down);
    cudaEventRecord(evTF, s2);
    k_ynode<<<NROW/8, 256, 0, s2>>>(Y_m, Y_t, pt, b_yn, g_yn, bn_yn, out);

    // s0: geometry chain
    k_atoms<<<NRES/256, 256>>>(X);
    cudaEventRecord(evAtoms, 0);

    // s2: vnode needs atoms + trans + fuse
    cudaStreamWaitEvent(s2, evAtoms, 0);
    k_vnode<<<NROW/64, 256, VN_SMF*4, s2>>>(Y, Y_t, pt, g_node, bn_node, out);
    cudaEventRecord(evS2, s2);

    // s0: topk then edge (edge also needs trans+fuse)
    k_topk<<<NRES, 256, 0, 0>>>(mask, out);
    cudaStreamWaitEvent(0, evTF, 0);
    k_edge<<<NEDGE/64, 256, EDGE_SMF*4, 0>>>(R_idx, chains, b_edge, g_edge, be_edge, out);

    // join
    cudaStreamWaitEvent(0, evS2, 0);
    cudaStreamWaitEvent(0, evS3, 0);
}

// round 14
// speedup vs baseline: 1.4669x; 1.0009x over previous
#include <cuda_runtime.h>
#include <cuda_bf16.h>

#define BB 2
#define LLEN 2048
#define MM 16
#define KNN 32
#define NRES (BB*LLEN)            // 4096
#define NEDGE (NRES*KNN)          // 131072
#define NROW (NRES*MM)            // 65536

static const size_t V_OFF  = 0;
static const size_t E_OFF  = (size_t)NROW*128;                  // 8388608
static const size_t EI_OFF = E_OFF + (size_t)NEDGE*128;         // 25165824
static const size_t YN_OFF = EI_OFF + (size_t)NEDGE;            // 25296896
static const size_t YE_OFF = YN_OFF + (size_t)NROW*128;         // 33685504
static const size_t YM_OFF = YE_OFF + (size_t)NRES*MM*MM*128;   // 167903232

typedef unsigned long long ull;

// ---------------- device scratch ----------------
__device__ float g_atoms[NRES*15];
__device__ float g_cax[NRES*3];
__device__ int   g_eidx[NEDGE];
__device__ float g_dnb[NEDGE];
__device__ float g_WeT[416*128];      // W_edge^T [f][n]
__device__ float g_WdTF[148*128];     // W_down^T full [f][n]
__device__ float g_WdT2[96*128];      // compact rows
__device__ float g_WynT[147*128];     // W_yn^T [f][c]
__device__ float g_Tpos[66*128];      // fused pos table
__device__ float g_Wfuse[147*128];    // Wt^T . Wd[:,80:144]^T
__device__ float g_btf[128];          // fused bias

// pairs (excluding leading D_neighbors block); atoms: N=0,Ca=1,C=2,O=3,Cb=4
__constant__ int c_PA24[24] = {0,2,3,4, 1,1,1,1, 0,0,0, 4,4, 3, 0,2,3,4, 2,3,4, 2,3, 2};
__constant__ int c_PB24[24] = {0,2,3,4, 0,2,3,4, 2,3,4, 2,3, 2, 1,1,1,1, 0,0,0, 4,4, 3};

// ---------------- f32x2 helpers ----------------
__device__ __forceinline__ ull pack2(float s) {
    ull r; asm("mov.b64 %0, {%1, %1};" : "=l"(r) : "r"(__float_as_uint(s))); return r;
}
__device__ __forceinline__ void ffma2(ull& a, ull s, ull w) {
    asm("fma.rn.f32x2 %0, %1, %2, %0;" : "+l"(a) : "l"(s), "l"(w));
}
__device__ __forceinline__ float2 unpack2(ull a) {
    unsigned lo, hi; asm("mov.b64 {%0, %1}, %2;" : "=r"(lo), "=r"(hi) : "l"(a));
    return make_float2(__uint_as_float(lo), __uint_as_float(hi));
}
__device__ __forceinline__ float4 ln128(float4 a, float4 g, float4 be) {
    float s  = a.x + a.y + a.z + a.w;
    float ss = fmaf(a.x,a.x, fmaf(a.y,a.y, fmaf(a.z,a.z, a.w*a.w)));
#pragma unroll
    for (int o = 16; o; o >>= 1) {
        s  += __shfl_xor_sync(0xffffffffu, s,  o);
        ss += __shfl_xor_sync(0xffffffffu, ss, o);
    }
    float mu   = s * 0.0078125f;
    float var  = ss * 0.0078125f - mu*mu;
    float rstd = rsqrtf(var + 1e-5f);
    float4 o4;
    o4.x = (a.x-mu)*rstd*g.x + be.x;
    o4.y = (a.y-mu)*rstd*g.y + be.y;
    o4.z = (a.z-mu)*rstd*g.z + be.z;
    o4.w = (a.w-mu)*rstd*g.w + be.w;
    return o4;
}

// 16 RBF values with 4 exps: anchor at nearest mu, geometric ratio chain.
__device__ __forceinline__ void rbf16(float D, float* dst, int stride) {
    const float DLT = 1.3333333333333333f;
    const float IS2 = 0.64f;
    const float C1  = 1.7066666666666668f;
    const float C2  = 1.1377777777777778f;
    float u = (D - 2.0f) * 0.75f;
    int rs = __float2int_rn(u);
    rs = rs < 0 ? 0 : (rs > 15 ? 15 : rs);
    float x = D - (2.0f + DLT * (float)rs);
    float peak  = __expf(-x*x*IS2);
    float fup   = __expf( C1*x - C2);
    float fdn   = __expf(-C1*x - C2);
    float decay = __expf(-2.0f*C2);
    float v = peak;
    dst[rs*stride] = v;
    float f = fup;
    for (int r = rs+1; r < 16; r++) { v *= f; dst[r*stride] = v; f *= decay; }
    v = peak; f = fdn;
    for (int r = rs-1; r >= 0; r--) { v *= f; dst[r*stride] = v; f *= decay; }
}

// ---------------- prep kernels ----------------
__global__ void k_atoms(const float* __restrict__ X) {
    int r = blockIdx.x*blockDim.x + threadIdx.x;
    if (r >= NRES) return;
    const float* x = X + (size_t)r*12;
    float nx=x[0],ny=x[1],nz=x[2], cax=x[3],cay=x[4],caz=x[5];
    float cxx=x[6],cyy=x[7],czz=x[8], ox=x[9],oy=x[10],oz=x[11];
    float bx=cax-nx, by=cay-ny, bz=caz-nz;
    float ccx=cxx-cax, ccy=cyy-cay, ccz=czz-caz;
    float ax=by*ccz-bz*ccy, ay=bz*ccx-bx*ccz, az=bx*ccy-by*ccx;
    float cbx=-0.58273431f*ax+0.56802827f*bx-0.54067466f*ccx+cax;
    float cby=-0.58273431f*ay+0.56802827f*by-0.54067466f*ccy+cay;
    float cbz=-0.58273431f*az+0.56802827f*bz-0.54067466f*ccz+caz;
    float* o = g_atoms + (size_t)r*15;
    o[0]=nx;o[1]=ny;o[2]=nz; o[3]=cax;o[4]=cay;o[5]=caz;
    o[6]=cxx;o[7]=cyy;o[8]=czz; o[9]=ox;o[10]=oy;o[11]=oz;
    o[12]=cbx;o[13]=cby;o[14]=cbz;
    g_cax[r*3+0]=cax; g_cax[r*3+1]=cay; g_cax[r*3+2]=caz;
}

__global__ void k_trans(const float* __restrict__ We, const float* __restrict__ Wd,
                        const float* __restrict__ Wyn) {
    int i = blockIdx.x*blockDim.x + threadIdx.x;
    if (i < 416*128) { int f=i>>7, n=i&127; g_WeT[i] = We[n*416+f]; return; }
    i -= 416*128;
    if (i < 148*128) { int f=i>>7, n=i&127; g_WdTF[i] = Wd[n*148+f]; return; }
    i -= 148*128;
    if (i < 96*128) {
        int f=i>>7, n=i&127;
        float v = 0.0f;
        if (f < 80) v = Wd[n*148+f];
        else if (f < 84) v = Wd[n*148+144+(f-80)];
        g_WdT2[i] = v; return;
    }
    i -= 96*128;
    if (i < 147*128) { int f=i>>7, c=i&127; g_WynT[i] = Wyn[c*147+f]; }
}

__global__ void k_fuse(const float* __restrict__ Wp, const float* __restrict__ bp,
                       const float* __restrict__ We, const float* __restrict__ Wt,
                       const float* __restrict__ bt, const float* __restrict__ bd) {
    int i = blockIdx.x*blockDim.x + threadIdx.x;
    if (i < 66*128) {
        int d = i>>7, n = i&127;
        float s = 0.0f;
        for (int c = 0; c < 16; c++) s = fmaf(Wp[c*66+d] + bp[c], We[n*416+c], s);
        g_Tpos[i] = s; return;
    }
    i -= 66*128;
    if (i < 147*128) {
        int f = i>>7, n = i&127;
        float s = 0.0f;
        for (int c = 0; c < 64; c++) s = fmaf(Wt[c*147+f], g_WdTF[(80+c)*128+n], s);
        g_Wfuse[i] = s; return;
    }
    i -= 147*128;
    if (i < 128) {
        float s = bd[i];
        for (int c = 0; c < 64; c++) s = fmaf(bt[c], g_WdTF[(80+c)*128+i], s);
        g_btf[i] = s;
    }
}

// ---------------- top-K neighbors: histogram pre-filter + exact warp selection ----------------
__global__ __launch_bounds__(256) void k_topk(const float* __restrict__ mask,
                                              float* __restrict__ out) {
    int row = blockIdx.x, b = row >> 11, t = threadIdx.x;
    int lane = t & 31, w = t >> 5;
    __shared__ float smax[8];
    __shared__ unsigned hist[256];
    __shared__ float pd[2048];
    __shared__ int   pj[2048];
    __shared__ int   scnt;
    __shared__ int   sthr;

    hist[t] = 0u;
    if (t == 0) scnt = 0;

    float cx = g_cax[row*3], cy = g_cax[row*3+1], cz = g_cax[row*3+2];
    float mi = mask[row];
    float dv[8], m2v[8];
    float lmax = -1e30f;
#pragma unroll
    for (int q = 0; q < 8; q++) {
        int jr = b*LLEN + t + (q<<8);
        float dx = cx - g_cax[jr*3], dy = cy - g_cax[jr*3+1], dz = cz - g_cax[jr*3+2];
        float dist = sqrtf(dx*dx + dy*dy + dz*dz + 1e-6f);
        float m2 = mi * mask[jr];
        dv[q] = m2 * dist; m2v[q] = m2;
        lmax = fmaxf(lmax, dv[q]);
    }
#pragma unroll
    for (int o = 16; o; o >>= 1) lmax = fmaxf(lmax, __shfl_xor_sync(0xffffffffu, lmax, o));
    if (lane == 0) smax[w] = lmax;
    __syncthreads();
    float dmax = fmaxf(fmaxf(fmaxf(smax[0],smax[1]),fmaxf(smax[2],smax[3])),
                       fmaxf(fmaxf(smax[4],smax[5]),fmaxf(smax[6],smax[7])));
    float inv = 256.0f / (dmax + 1e-6f);
#pragma unroll
    for (int q = 0; q < 8; q++) {
        dv[q] += (1.0f - m2v[q]) * dmax;
        int bq = (int)(dv[q] * inv);
        bq = bq < 0 ? 0 : (bq > 255 ? 255 : bq);
        atomicAdd(&hist[bq], 1u);
    }
    __syncthreads();

    if (w == 0) {
        unsigned s = 0;
#pragma unroll
        for (int k = 0; k < 8; k++) s += hist[lane*8 + k];
        unsigned scan = s;
#pragma unroll
        for (int o = 1; o < 32; o <<= 1) {
            unsigned v = __shfl_up_sync(0xffffffffu, scan, o);
            if (lane >= o) scan += v;
        }
        unsigned ballot = __ballot_sync(0xffffffffu, scan >= KNN);
        int fl = __ffs(ballot) - 1;
        if (lane == fl) {
            unsigned cum = scan - s;
            int bt_ = lane*8;
            for (int k = 0; k < 8; k++) {
                cum += hist[lane*8 + k];
                if (cum >= KNN) { bt_ = lane*8 + k; break; }
            }
            sthr = bt_;
        }
    }
    __syncthreads();

    int thr = sthr;
#pragma unroll
    for (int q = 0; q < 8; q++) {
        int bq = (int)(dv[q] * inv);
        bq = bq < 0 ? 0 : (bq > 255 ? 255 : bq);
        if (bq <= thr) {
            int p = atomicAdd(&scnt, 1);
            pd[p] = dv[q];
            pj[p] = t + (q<<8);
        }
    }
    __syncthreads();

    if (w == 0) {
        int n = scnt;
        for (int it = 0; it < KNN; it++) {
            float bv = 3e38f; int bj = 0x7fffffff; int bp = -1;
            for (int i = lane; i < n; i += 32) {
                float v = pd[i]; int j = pj[i];
                if (v < bv || (v == bv && j < bj)) { bv = v; bj = j; bp = i; }
            }
            float rv = bv; int rj = bj;
#pragma unroll
            for (int o = 16; o; o >>= 1) {
                float ov = __shfl_xor_sync(0xffffffffu, rv, o);
                int   oj = __shfl_xor_sync(0xffffffffu, rj, o);
                if (ov < rv || (ov == rv && oj < rj)) { rv = ov; rj = oj; }
            }
            if (bp >= 0 && rv == bv && rj == bj) pd[bp] = 3e38f;
            if (lane == 0) {
                g_eidx[(size_t)row*KNN + it] = rj;
                g_dnb [(size_t)row*KNN + it] = rv;
                out[EI_OFF + (size_t)row*KNN + it] = (float)rj;
            }
            __syncwarp();
        }
    }
}

// ---------------- Edge: features + GEMM(400->128, W via L1/L2) + Tpos + LN ----------------
#define EFEAT_ROWS 144
#define EDGE_SMF (EFEAT_ROWS*64 + 32 + 960 + 64 + 64 + 64)   // 10400 floats = 41.6KB
__global__ __launch_bounds__(256, 3) void k_edge(
    const int* __restrict__ R_idx, const int* __restrict__ chains,
    const float* __restrict__ b_edge, const float* __restrict__ g_edge,
    const float* __restrict__ be_edge, float* __restrict__ out) {
    extern __shared__ float sm[];
    float* feats = sm;                       // [144][64]
    float* ai    = sm + EFEAT_ROWS*64;       // 32
    float* aj    = ai + 32;                  // [64][15]
    float* dnb   = aj + 960;                 // 64
    int*   sJ    = (int*)(dnb + 64);         // 64
    int*   sdc   = sJ + 64;                  // 64

    int t = threadIdx.x;
    int r0 = blockIdx.x * 2;
    int b  = r0 >> 11;
    int ebase = blockIdx.x * 64;
    int lane = t & 31, w = t >> 5;

    if (t < 30) ai[t] = g_atoms[r0*15 + t];
    if (t < 64) { sJ[t] = g_eidx[ebase + t]; dnb[t] = g_dnb[ebase + t]; }
    __syncthreads();
    for (int k = t; k < 960; k += 256) {
        int e = k / 15, c = k % 15;
        aj[k] = g_atoms[(size_t)(b*LLEN + sJ[e])*15 + c];
    }
    if (t < 64) {
        int ig = r0 + (t >> 5);
        int jg = b*LLEN + sJ[t];
        int off = R_idx[ig] - R_idx[jg];
        int ec  = (chains[ig] == chains[jg]);
        int d = off + 32; d = d < 0 ? 0 : (d > 64 ? 64 : d);
        sdc[t] = ec ? d : 65;
    }
    __syncthreads();

    ull acc[16];
    {
        float4 b4 = ((const float4*)b_edge)[lane];
        ull b0 = pack2(b4.x), b1 = pack2(b4.y), b2 = pack2(b4.z), b3 = pack2(b4.w);
#pragma unroll
        for (int p = 0; p < 4; p++) { acc[p*4]=b0; acc[p*4+1]=b1; acc[p*4+2]=b2; acc[p*4+3]=b3; }
    }

    int pbase = 0;
    for (int ph = 0; ph < 3; ph++) {
        int P = ph ? 8 : 9;
        {
            int e = t & 63, psub = t >> 6;
            const float* A  = ai + (e >> 5) * 15;
            const float* Bv = aj + e * 15;
            for (int p = psub; p < P; p += 4) {
                int gp = pbase + p;
                float D;
                if (gp == 0) D = dnb[e];
                else {
                    int pa = c_PA24[gp-1]*3, pb = c_PB24[gp-1]*3;
                    float dx=A[pa]-Bv[pb], dy=A[pa+1]-Bv[pb+1], dz=A[pa+2]-Bv[pb+2];
                    D = sqrtf(dx*dx + dy*dy + dz*dz + 1e-6f);
                }
                rbf16(D, &feats[(p*16)*64 + e], 64);
            }
        }
        __syncthreads();                 // feats ready for this phase
        for (int kc = 0; kc < P; kc++) {
            const float4* Wg = (const float4*)g_WeT + (size_t)(pbase+kc+1)*512 + lane;
            const float* fb = feats + (kc*16)*64 + 8*w;
#pragma unroll
            for (int fi = 0; fi < 16; fi++) {
                float4 w4 = __ldg(&Wg[fi*32]);
                ulonglong2 f01 = *(const ulonglong2*)&fb[fi*64];
                ulonglong2 f23 = *(const ulonglong2*)&fb[fi*64 + 4];
                ull w0 = pack2(w4.x), w1 = pack2(w4.y), w2 = pack2(w4.z), w3 = pack2(w4.w);
                ffma2(acc[0],  f01.x, w0); ffma2(acc[1],  f01.x, w1);
                ffma2(acc[2],  f01.x, w2); ffma2(acc[3],  f01.x, w3);
                ffma2(acc[4],  f01.y, w0); ffma2(acc[5],  f01.y, w1);
                ffma2(acc[6],  f01.y, w2); ffma2(acc[7],  f01.y, w3);
                ffma2(acc[8],  f23.x, w0); ffma2(acc[9],  f23.x, w1);
                ffma2(acc[10], f23.x, w2); ffma2(acc[11], f23.x, w3);
                ffma2(acc[12], f23.y, w0); ffma2(acc[13], f23.y, w1);
                ffma2(acc[14], f23.y, w2); ffma2(acc[15], f23.y, w3);
            }
        }
        __syncthreads();                 // protect feats before next phase writes
        pbase += P;
    }

    float4 g4  = ((const float4*)g_edge)[lane];
    float4 be4 = ((const float4*)be_edge)[lane];
    float4* o4 = (float4*)(out + E_OFF);
#pragma unroll
    for (int p = 0; p < 4; p++) {
        float2 u0 = unpack2(acc[p*4]);
        float2 u1 = unpack2(acc[p*4+1]);
        float2 u2 = unpack2(acc[p*4+2]);
        float2 u3 = unpack2(acc[p*4+3]);
        int e0 = 8*w + 2*p, e1 = e0 + 1;
        float4 tp0 = ((const float4*)g_Tpos)[sdc[e0]*32 + lane];
        float4 tp1 = ((const float4*)g_Tpos)[sdc[e1]*32 + lane];
        float4 a0 = make_float4(u0.x+tp0.x, u1.x+tp0.y, u2.x+tp0.z, u3.x+tp0.w);
        float4 a1 = make_float4(u0.y+tp1.x, u1.y+tp1.y, u2.y+tp1.z, u3.y+tp1.w);
        float4 r0v = ln128(a0, g4, be4);
        float4 r1v = ln128(a1, g4, be4);
        o4[(size_t)(ebase+e0)*32 + lane] = r0v;
        o4[(size_t)(ebase+e1)*32 + lane] = r1v;
    }
}

// ---------------- V node: features + GEMM(96->128, W via L1/L2) + fuse + LN ----------------
#define VN_SMF (96*64 + 64 + 192 + 36 + 192)   // 6628 floats = 26.5KB
__global__ __launch_bounds__(256, 3) void k_vnode(
    const float* __restrict__ Y, const int* __restrict__ Y_t, const int* __restrict__ pt,
    const float* __restrict__ g_node, const float* __restrict__ bn_node,
    float* __restrict__ out) {
    extern __shared__ float sm[];
    float* feats = sm;                    // [96][64]
    float* at    = sm + 96*64;            // [4][15] pad 64
    float* ys    = at + 64;               // [64][3]
    float* fr    = ys + 192;              // [4][9]
    int*   cols  = (int*)(fr + 36);       // [64][3]

    int t = threadIdx.x;
    int bid = blockIdx.x;
    int rbase = bid * 4;
    int rowg0 = bid * 64;
    int lane = t & 31, w = t >> 5;

    if (t < 60) at[t] = g_atoms[(size_t)rbase*15 + t];
    if (t < 192) ys[t] = Y[(size_t)rowg0*3 + t];
    if (t < 64) {
        int yt = Y_t[rowg0 + t];
        cols[t*3+0] = yt;
        cols[t*3+1] = 120 + pt[120 + yt];
        cols[t*3+2] = 139 + pt[240 + yt];
    }
    for (int idx = t; idx < 12*64; idx += 256) feats[84*64 + idx] = 0.0f;
    __syncthreads();
    if (t < 4) {
        const float* A = at + t*15;
        float v1x=A[0]-A[3], v1y=A[1]-A[4], v1z=A[2]-A[5];
        float v2x=A[6]-A[3], v2y=A[7]-A[4], v2z=A[8]-A[5];
        float n1 = sqrtf(v1x*v1x+v1y*v1y+v1z*v1z) + 1e-8f;
        float e1x=v1x/n1, e1y=v1y/n1, e1z=v1z/n1;
        float d12 = e1x*v2x + e1y*v2y + e1z*v2z;
        float ux=v2x-e1x*d12, uy=v2y-e1y*d12, uz=v2z-e1z*d12;
        float n2 = sqrtf(ux*ux+uy*uy+uz*uz) + 1e-8f;
        float e2x=ux/n2, e2y=uy/n2, e2z=uz/n2;
        float e3x=e1y*e2z-e1z*e2y, e3y=e1z*e2x-e1x*e2z, e3z=e1x*e2y-e1y*e2x;
        float* F = fr + t*9;
        F[0]=e1x;F[1]=e1y;F[2]=e1z; F[3]=e2x;F[4]=e2y;F[5]=e2z; F[6]=e3x;F[7]=e3y;F[8]=e3z;
    }
    {
        int row = t & 63, res = row >> 4;
        const float* yy = ys + row*3;
        for (int p = t >> 6; p < 5; p += 4) {
            const float* A = at + res*15 + p*3;
            float dx=A[0]-yy[0], dy=A[1]-yy[1], dz=A[2]-yy[2];
            float D = sqrtf(dx*dx+dy*dy+dz*dz + 1e-6f);
            rbf16(D, &feats[(p*16)*64 + row], 64);
        }
    }
    __syncthreads();
    if (t < 64) {
        int row = t, res = row >> 4;
        const float* F = fr + res*9;
        float dx = ys[row*3]   - at[res*15+3];
        float dy = ys[row*3+1] - at[res*15+4];
        float dz = ys[row*3+2] - at[res*15+5];
        float lv0 = F[0]*dx+F[1]*dy+F[2]*dz;
        float lv1 = F[3]*dx+F[4]*dy+F[5]*dz;
        float lv2 = F[6]*dx+F[7]*dy+F[8]*dz;
        float rxy  = sqrtf(lv0*lv0 + lv1*lv1 + 1e-8f);
        float rxyz = sqrtf(lv0*lv0 + lv1*lv1 + lv2*lv2) + 1e-8f;
        feats[80*64+row] = lv0/rxy;
        feats[81*64+row] = lv1/rxy;
        feats[82*64+row] = rxy/rxyz;
        feats[83*64+row] = lv2/rxyz;
    }
    __syncthreads();
    ull acc[16];
    {
        float4 b4 = ((const float4*)g_btf)[lane];
        ull b0 = pack2(b4.x), b1 = pack2(b4.y), b2 = pack2(b4.z), b3 = pack2(b4.w);
#pragma unroll
        for (int p = 0; p < 4; p++) { acc[p*4]=b0; acc[p*4+1]=b1; acc[p*4+2]=b2; acc[p*4+3]=b3; }
    }
    for (int kc = 0; kc < 6; kc++) {
        const float4* Wg = (const float4*)g_WdT2 + (size_t)kc*512 + lane;
        const float* fb = feats + (kc*16)*64 + 8*w;
#pragma unroll
        for (int fi = 0; fi < 16; fi++) {
            float4 w4 = __ldg(&Wg[fi*32]);
            ulonglong2 f01 = *(const ulonglong2*)&fb[fi*64];
            ulonglong2 f23 = *(const ulonglong2*)&fb[fi*64 + 4];
            ull w0 = pack2(w4.x), w1 = pack2(w4.y), w2 = pack2(w4.z), w3 = pack2(w4.w);
            ffma2(acc[0],  f01.x, w0); ffma2(acc[1],  f01.x, w1);
            ffma2(acc[2],  f01.x, w2); ffma2(acc[3],  f01.x, w3);
            ffma2(acc[4],  f01.y, w0); ffma2(acc[5],  f01.y, w1);
            ffma2(acc[6],  f01.y, w2); ffma2(acc[7],  f01.y, w3);
            ffma2(acc[8],  f23.x, w0); ffma2(acc[9],  f23.x, w1);
            ffma2(acc[10], f23.x, w2); ffma2(acc[11], f23.x, w3);
            ffma2(acc[12], f23.y, w0); ffma2(acc[13], f23.y, w1);
            ffma2(acc[14], f23.y, w2); ffma2(acc[15], f23.y, w3);
        }
    }
    float4 g4  = ((const float4*)g_node)[lane];
    float4 be4 = ((const float4*)bn_node)[lane];
    float4* o4 = (float4*)(out + V_OFF);
#pragma unroll
    for (int p = 0; p < 4; p++) {
        float2 u0 = unpack2(acc[p*4]);
        float2 u1 = unpack2(acc[p*4+1]);
        float2 u2 = unpack2(acc[p*4+2]);
        float2 u3 = unpack2(acc[p*4+3]);
        int e0 = 8*w + 2*p, e1 = e0 + 1;
        float4 a0 = make_float4(u0.x, u1.x, u2.x, u3.x);
        float4 a1 = make_float4(u0.y, u1.y, u2.y, u3.y);
#pragma unroll
        for (int j = 0; j < 3; j++) {
            float4 q0 = ((const float4*)g_Wfuse)[cols[e0*3+j]*32 + lane];
            float4 q1 = ((const float4*)g_Wfuse)[cols[e1*3+j]*32 + lane];
            a0.x+=q0.x; a0.y+=q0.y; a0.z+=q0.z; a0.w+=q0.w;
            a1.x+=q1.x; a1.y+=q1.y; a1.z+=q1.z; a1.w+=q1.w;
        }
        float4 r0v = ln128(a0, g4, be4);
        float4 r1v = ln128(a1, g4, be4);
        o4[(size_t)(rowg0+e0)*32 + lane] = r0v;
        o4[(size_t)(rowg0+e1)*32 + lane] = r1v;
    }
}

// ---------------- Y_nodes (gather + LN) + Y_m copy ----------------
__global__ __launch_bounds__(256) void k_ynode(
    const float* __restrict__ Y_m, const int* __restrict__ Y_t, const int* __restrict__ pt,
    const float* __restrict__ b_yn, const float* __restrict__ g_yn,
    const float* __restrict__ bn_yn, float* __restrict__ out) {
    int t = threadIdx.x, lane = t & 31, w = t >> 5;
    int row = blockIdx.x*8 + w;
    int yt = Y_t[row];
    int c0 = yt, c1 = 120 + pt[120+yt], c2 = 139 + pt[240+yt];
    float4 a  = ((const float4*)&g_WynT[(size_t)c0*128])[lane];
    float4 a1 = ((const float4*)&g_WynT[(size_t)c1*128])[lane];
    float4 a2 = ((const float4*)&g_WynT[(size_t)c2*128])[lane];
    float4 b4 = ((const float4*)b_yn)[lane];
    a.x += a1.x + a2.x + b4.x;
    a.y += a1.y + a2.y + b4.y;
    a.z += a1.z + a2.z + b4.z;
    a.w += a1.w + a2.w + b4.w;
    float4 g4  = ((const float4*)g_yn)[lane];
    float4 be4 = ((const float4*)bn_yn)[lane];
    float4 r = ln128(a, g4, be4);
    ((float4*)(out + YN_OFF))[(size_t)row*32 + lane] = r;
    if (lane == 0) out[YM_OFF + row] = Y_m[row];
}

// ---------------- Y_edges: symmetric pairs, 16->128 + LN ----------------
__global__ __launch_bounds__(256) void k_yedge(
    const float* __restrict__ Y, const float* __restrict__ W_ye,
    const float* __restrict__ b_ye, const float* __restrict__ g_ye,
    const float* __restrict__ bn_ye, float* __restrict__ out) {
    __shared__ float ys[48];
    __shared__ float rbfs[136*16];
    __shared__ float WyeS[16*128];
    __shared__ int sm1[136], sm2[136];
    int t = threadIdx.x, bl = blockIdx.x;
    if (t < 48) ys[t] = Y[(size_t)bl*48 + t];
    for (int i = t; i < 2048; i += 256) {
        int c = i >> 4, r = i & 15;
        WyeS[r*128 + c] = W_ye[i];
    }
    if (t < 136) {
        int u = t, m1 = 0;
        while (u >= 16 - m1) { u -= 16 - m1; m1++; }
        sm1[t] = m1; sm2[t] = m1 + u;
    }
    __syncthreads();
    if (t < 136) {
        int m1 = sm1[t], m2 = sm2[t];
        float dx = ys[m1*3]-ys[m2*3], dy = ys[m1*3+1]-ys[m2*3+1], dz = ys[m1*3+2]-ys[m2*3+2];
        float D = sqrtf(dx*dx + dy*dy + dz*dz + 1e-6f);
        rbf16(D, &rbfs[t*16], 1);
    }
    __syncthreads();
    int lane = t & 31, w = t >> 5;
    float4 bye4 = ((const float4*)b_ye)[lane];
    float4 g4   = ((const float4*)g_ye)[lane];
    float4 be4  = ((const float4*)bn_ye)[lane];
    float4* o4 = (float4*)out;
    size_t yebase4 = YE_OFF >> 2;
    for (int u = w; u < 136; u += 8) {
        float4 a = bye4;
#pragma unroll
        for (int r = 0; r < 16; r++) {
            float rb = rbfs[u*16 + r];
            float4 wv = ((const float4*)&WyeS[r*128])[lane];
            a.x = fmaf(rb, wv.x, a.x); a.y = fmaf(rb, wv.y, a.y);
            a.z = fmaf(rb, wv.z, a.z); a.w = fmaf(rb, wv.w, a.w);
        }
        float4 res = ln128(a, g4, be4);
        int m1 = sm1[u], m2 = sm2[u];
        size_t r1 = (size_t)bl*256 + m1*16 + m2;
        size_t r2 = (size_t)bl*256 + m2*16 + m1;
        o4[yebase4 + r1*32 + lane] = res;
        if (r2 != r1) o4[yebase4 + r2*32 + lane] = res;
    }
}

// ---------------- launch: multi-stream DAG; yedge overlapped with edge ----------------
extern "C" void kernel_launch(void* const* d_in, const int* in_sizes, int n_in,
                              void* d_out, int out_size) {
    const float* X        = (const float*)d_in[0];
    const float* Y        = (const float*)d_in[1];
    const float* Y_m      = (const float*)d_in[2];
    const float* mask     = (const float*)d_in[3];
    const float* W_pos    = (const float*)d_in[4];
    const float* b_pos    = (const float*)d_in[5];
    const float* W_edge   = (const float*)d_in[6];
    const float* b_edge   = (const float*)d_in[7];
    const float* g_edge   = (const float*)d_in[8];
    const float* be_edge  = (const float*)d_in[9];
    const float* W_down   = (const float*)d_in[10];
    const float* b_down   = (const float*)d_in[11];
    const float* g_node   = (const float*)d_in[12];
    const float* bn_node  = (const float*)d_in[13];
    const float* W_type   = (const float*)d_in[14];
    const float* b_type   = (const float*)d_in[15];
    const float* W_yn     = (const float*)d_in[16];
    const float* b_yn     = (const float*)d_in[17];
    const float* g_yn     = (const float*)d_in[18];
    const float* bn_yn    = (const float*)d_in[19];
    const float* W_ye     = (const float*)d_in[20];
    const float* b_ye     = (const float*)d_in[21];
    const float* g_ye     = (const float*)d_in[22];
    const float* bn_ye    = (const float*)d_in[23];
    const int*   Y_t      = (const int*)d_in[24];
    const int*   R_idx    = (const int*)d_in[25];
    const int*   chains   = (const int*)d_in[26];
    const int*   pt       = (const int*)d_in[27];
    float* out = (float*)d_out;

    static bool init_done = false;
    static cudaStream_t s2, s3;
    static cudaEvent_t evRoot, evAtoms, evTF, evTopk, evS2, evS3;
    if (!init_done) {
        cudaStreamCreateWithFlags(&s2, cudaStreamNonBlocking);
        cudaStreamCreateWithFlags(&s3, cudaStreamNonBlocking);
        cudaEventCreateWithFlags(&evRoot,  cudaEventDisableTiming);
        cudaEventCreateWithFlags(&evAtoms, cudaEventDisableTiming);
        cudaEventCreateWithFlags(&evTF,    cudaEventDisableTiming);
        cudaEventCreateWithFlags(&evTopk,  cudaEventDisableTiming);
        cudaEventCreateWithFlags(&evS2,    cudaEventDisableTiming);
        cudaEventCreateWithFlags(&evS3,    cudaEventDisableTiming);
        cudaFuncSetAttribute(k_edge,  cudaFuncAttributeMaxDynamicSharedMemorySize, EDGE_SMF*4);
        cudaFuncSetAttribute(k_vnode, cudaFuncAttributeMaxDynamicSharedMemorySize, VN_SMF*4);
        init_done = true;
    }

    // fork from origin stream
    cudaEventRecord(evRoot, 0);
    cudaStreamWaitEvent(s2, evRoot, 0);
    cudaStreamWaitEvent(s3, evRoot, 0);

    // s2: weight prep chain + ynode (runs concurrent with topk)
    k_trans<<<(416*128 + 148*128 + 96*128 + 147*128 + 255)/256, 256, 0, s2>>>(W_edge, W_down, W_yn);
    k_fuse<<<(66*128 + 147*128 + 128 + 255)/256, 256, 0, s2>>>(W_pos, b_pos, W_edge, W_type, b_type, b_down);
    cudaEventRecord(evTF, s2);
    k_ynode<<<NROW/8, 256, 0, s2>>>(Y_m, Y_t, pt, b_yn, g_yn, bn_yn, out);

    // s0: geometry chain
    k_atoms<<<NRES/256, 256>>>(X);
    cudaEventRecord(evAtoms, 0);

    // s2: vnode needs atoms + trans + fuse (runs concurrent with topk/edge)
    cudaStreamWaitEvent(s2, evAtoms, 0);
    k_vnode<<<NROW/64, 256, VN_SMF*4, s2>>>(Y, Y_t, pt, g_node, bn_node, out);
    cudaEventRecord(evS2, s2);

    // s0: topk then edge (edge also needs trans+fuse)
    k_topk<<<NRES, 256, 0, 0>>>(mask, out);
    cudaEventRecord(evTopk, 0);
    cudaStreamWaitEvent(0, evTF, 0);
    k_edge<<<NEDGE/64, 256, EDGE_SMF*4, 0>>>(R_idx, chains, b_edge, g_edge, be_edge, out);

    // s3: yedge delayed to co-run with edge (DRAM-bound vs FMA-bound)
    cudaStreamWaitEvent(s3, evTopk, 0);
    k_yedge<<<BB*LLEN, 256, 0, s3>>>(Y, W_ye, b_ye, g_ye, bn_ye, out);
    cudaEventRecord(evS3, s3);

    // join
    cudaStreamWaitEvent(0, evS2, 0);
    cudaStreamWaitEvent(0, evS3, 0);
}

// round 15
// speedup vs baseline: 1.6319x; 1.1124x over previous
#include <cuda_runtime.h>
#include <cuda_bf16.h>

#define BB 2
#define LLEN 2048
#define MM 16
#define KNN 32
#define NRES (BB*LLEN)            // 4096
#define NEDGE (NRES*KNN)          // 131072
#define NROW (NRES*MM)            // 65536

static const size_t V_OFF  = 0;
static const size_t E_OFF  = (size_t)NROW*128;                  // 8388608
static const size_t EI_OFF = E_OFF + (size_t)NEDGE*128;         // 25165824
static const size_t YN_OFF = EI_OFF + (size_t)NEDGE;            // 25296896
static const size_t YE_OFF = YN_OFF + (size_t)NROW*128;         // 33685504
static const size_t YM_OFF = YE_OFF + (size_t)NRES*MM*MM*128;   // 167903232

typedef unsigned long long ull;

// ---------------- device scratch ----------------
__device__ float g_atoms[NRES*15];
__device__ float g_cax[NRES*3];
__device__ int   g_eidx[NEDGE];
__device__ float g_dnb[NEDGE];
__device__ float g_WeT[416*128];      // W_edge^T [f][n]
__device__ float g_WdTF[148*128];     // W_down^T full [f][n]
__device__ float g_WdT2[96*128];      // compact rows
__device__ float g_WynT[147*128];     // W_yn^T [f][c]
__device__ float g_Tpos[66*128];      // fused pos table
__device__ float g_Wfuse[147*128];    // Wt^T . Wd[:,80:144]^T
__device__ float g_btf[128];          // fused bias

// pairs (excluding leading D_neighbors block); atoms: N=0,Ca=1,C=2,O=3,Cb=4
__constant__ int c_PA24[24] = {0,2,3,4, 1,1,1,1, 0,0,0, 4,4, 3, 0,2,3,4, 2,3,4, 2,3, 2};
__constant__ int c_PB24[24] = {0,2,3,4, 0,2,3,4, 2,3,4, 2,3, 2, 1,1,1,1, 0,0,0, 4,4, 3};

// ---------------- f32x2 helpers ----------------
__device__ __forceinline__ ull pack2(float s) {
    ull r; asm("mov.b64 %0, {%1, %1};" : "=l"(r) : "r"(__float_as_uint(s))); return r;
}
__device__ __forceinline__ void ffma2(ull& a, ull s, ull w) {
    asm("fma.rn.f32x2 %0, %1, %2, %0;" : "+l"(a) : "l"(s), "l"(w));
}
__device__ __forceinline__ float2 unpack2(ull a) {
    unsigned lo, hi; asm("mov.b64 {%0, %1}, %2;" : "=r"(lo), "=r"(hi) : "l"(a));
    return make_float2(__uint_as_float(lo), __uint_as_float(hi));
}
__device__ __forceinline__ float4 ln128(float4 a, float4 g, float4 be) {
    float s  = a.x + a.y + a.z + a.w;
    float ss = fmaf(a.x,a.x, fmaf(a.y,a.y, fmaf(a.z,a.z, a.w*a.w)));
#pragma unroll
    for (int o = 16; o; o >>= 1) {
        s  += __shfl_xor_sync(0xffffffffu, s,  o);
        ss += __shfl_xor_sync(0xffffffffu, ss, o);
    }
    float mu   = s * 0.0078125f;
    float var  = ss * 0.0078125f - mu*mu;
    float rstd = rsqrtf(var + 1e-5f);
    float4 o4;
    o4.x = (a.x-mu)*rstd*g.x + be.x;
    o4.y = (a.y-mu)*rstd*g.y + be.y;
    o4.z = (a.z-mu)*rstd*g.z + be.z;
    o4.w = (a.w-mu)*rstd*g.w + be.w;
    return o4;
}

// 16 RBF values with 4 exps: anchor at nearest mu, geometric ratio chain.
__device__ __forceinline__ void rbf16(float D, float* dst, int stride) {
    const float DLT = 1.3333333333333333f;
    const float IS2 = 0.64f;
    const float C1  = 1.7066666666666668f;
    const float C2  = 1.1377777777777778f;
    float u = (D - 2.0f) * 0.75f;
    int rs = __float2int_rn(u);
    rs = rs < 0 ? 0 : (rs > 15 ? 15 : rs);
    float x = D - (2.0f + DLT * (float)rs);
    float peak  = __expf(-x*x*IS2);
    float fup   = __expf( C1*x - C2);
    float fdn   = __expf(-C1*x - C2);
    float decay = __expf(-2.0f*C2);
    float v = peak;
    dst[rs*stride] = v;
    float f = fup;
    for (int r = rs+1; r < 16; r++) { v *= f; dst[r*stride] = v; f *= decay; }
    v = peak; f = fdn;
    for (int r = rs-1; r >= 0; r--) { v *= f; dst[r*stride] = v; f *= decay; }
}

// ---------------- prep kernels ----------------
__global__ void k_atoms(const float* __restrict__ X) {
    int r = blockIdx.x*blockDim.x + threadIdx.x;
    if (r >= NRES) return;
    const float* x = X + (size_t)r*12;
    float nx=x[0],ny=x[1],nz=x[2], cax=x[3],cay=x[4],caz=x[5];
    float cxx=x[6],cyy=x[7],czz=x[8], ox=x[9],oy=x[10],oz=x[11];
    float bx=cax-nx, by=cay-ny, bz=caz-nz;
    float ccx=cxx-cax, ccy=cyy-cay, ccz=czz-caz;
    float ax=by*ccz-bz*ccy, ay=bz*ccx-bx*ccz, az=bx*ccy-by*ccx;
    float cbx=-0.58273431f*ax+0.56802827f*bx-0.54067466f*ccx+cax;
    float cby=-0.58273431f*ay+0.56802827f*by-0.54067466f*ccy+cay;
    float cbz=-0.58273431f*az+0.56802827f*bz-0.54067466f*ccz+caz;
    float* o = g_atoms + (size_t)r*15;
    o[0]=nx;o[1]=ny;o[2]=nz; o[3]=cax;o[4]=cay;o[5]=caz;
    o[6]=cxx;o[7]=cyy;o[8]=czz; o[9]=ox;o[10]=oy;o[11]=oz;
    o[12]=cbx;o[13]=cby;o[14]=cbz;
    g_cax[r*3+0]=cax; g_cax[r*3+1]=cay; g_cax[r*3+2]=caz;
}

__global__ void k_trans(const float* __restrict__ We, const float* __restrict__ Wd,
                        const float* __restrict__ Wyn) {
    int i = blockIdx.x*blockDim.x + threadIdx.x;
    if (i < 416*128) { int f=i>>7, n=i&127; g_WeT[i] = We[n*416+f]; return; }
    i -= 416*128;
    if (i < 148*128) { int f=i>>7, n=i&127; g_WdTF[i] = Wd[n*148+f]; return; }
    i -= 148*128;
    if (i < 96*128) {
        int f=i>>7, n=i&127;
        float v = 0.0f;
        if (f < 80) v = Wd[n*148+f];
        else if (f < 84) v = Wd[n*148+144+(f-80)];
        g_WdT2[i] = v; return;
    }
    i -= 96*128;
    if (i < 147*128) { int f=i>>7, c=i&127; g_WynT[i] = Wyn[c*147+f]; }
}

__global__ void k_fuse(const float* __restrict__ Wp, const float* __restrict__ bp,
                       const float* __restrict__ We, const float* __restrict__ Wt,
                       const float* __restrict__ bt, const float* __restrict__ bd) {
    int i = blockIdx.x*blockDim.x + threadIdx.x;
    if (i < 66*128) {
        int d = i>>7, n = i&127;
        float s = 0.0f;
        for (int c = 0; c < 16; c++) s = fmaf(Wp[c*66+d] + bp[c], We[n*416+c], s);
        g_Tpos[i] = s; return;
    }
    i -= 66*128;
    if (i < 147*128) {
        int f = i>>7, n = i&127;
        float s = 0.0f;
        for (int c = 0; c < 64; c++) s = fmaf(Wt[c*147+f], g_WdTF[(80+c)*128+n], s);
        g_Wfuse[i] = s; return;
    }
    i -= 147*128;
    if (i < 128) {
        float s = bd[i];
        for (int c = 0; c < 64; c++) s = fmaf(bt[c], g_WdTF[(80+c)*128+i], s);
        g_btf[i] = s;
    }
}

// ---------------- top-K neighbors: histogram pre-filter + parallel rank selection ----------------
__global__ __launch_bounds__(256) void k_topk(const float* __restrict__ mask,
                                              float* __restrict__ out) {
    int row = blockIdx.x, b = row >> 11, t = threadIdx.x;
    int lane = t & 31, w = t >> 5;
    __shared__ float smax[8];
    __shared__ unsigned hist[256];
    __shared__ float pd[2048];
    __shared__ int   pj[2048];
    __shared__ int   scnt;
    __shared__ int   sthr;

    hist[t] = 0u;
    if (t == 0) scnt = 0;

    float cx = g_cax[row*3], cy = g_cax[row*3+1], cz = g_cax[row*3+2];
    float mi = mask[row];
    float dv[8], m2v[8];
    float lmax = -1e30f;
#pragma unroll
    for (int q = 0; q < 8; q++) {
        int jr = b*LLEN + t + (q<<8);
        float dx = cx - g_cax[jr*3], dy = cy - g_cax[jr*3+1], dz = cz - g_cax[jr*3+2];
        float dist = sqrtf(dx*dx + dy*dy + dz*dz + 1e-6f);
        float m2 = mi * mask[jr];
        dv[q] = m2 * dist; m2v[q] = m2;
        lmax = fmaxf(lmax, dv[q]);
    }
#pragma unroll
    for (int o = 16; o; o >>= 1) lmax = fmaxf(lmax, __shfl_xor_sync(0xffffffffu, lmax, o));
    if (lane == 0) smax[w] = lmax;
    __syncthreads();
    float dmax = fmaxf(fmaxf(fmaxf(smax[0],smax[1]),fmaxf(smax[2],smax[3])),
                       fmaxf(fmaxf(smax[4],smax[5]),fmaxf(smax[6],smax[7])));
    float inv = 256.0f / (dmax + 1e-6f);
#pragma unroll
    for (int q = 0; q < 8; q++) {
        dv[q] += (1.0f - m2v[q]) * dmax;
        int bq = (int)(dv[q] * inv);
        bq = bq < 0 ? 0 : (bq > 255 ? 255 : bq);
        atomicAdd(&hist[bq], 1u);
    }
    __syncthreads();

    if (w == 0) {
        unsigned s = 0;
#pragma unroll
        for (int k = 0; k < 8; k++) s += hist[lane*8 + k];
        unsigned scan = s;
#pragma unroll
        for (int o = 1; o < 32; o <<= 1) {
            unsigned v = __shfl_up_sync(0xffffffffu, scan, o);
            if (lane >= o) scan += v;
        }
        unsigned ballot = __ballot_sync(0xffffffffu, scan >= KNN);
        int fl = __ffs(ballot) - 1;
        if (lane == fl) {
            unsigned cum = scan - s;
            int bt_ = lane*8;
            for (int k = 0; k < 8; k++) {
                cum += hist[lane*8 + k];
                if (cum >= KNN) { bt_ = lane*8 + k; break; }
            }
            sthr = bt_;
        }
    }
    __syncthreads();

    int thr = sthr;
#pragma unroll
    for (int q = 0; q < 8; q++) {
        int bq = (int)(dv[q] * inv);
        bq = bq < 0 ? 0 : (bq > 255 ? 255 : bq);
        if (bq <= thr) {
            int p = atomicAdd(&scnt, 1);
            pd[p] = dv[q];
            pj[p] = t + (q<<8);
        }
    }
    __syncthreads();

    // parallel exact rank-by-counting over the compacted superset:
    // keys (dist, j) are unique; rank < KNN -> write that output slot directly.
    int n = scnt;
    for (int i = t; i < n; i += 256) {
        float di = pd[i]; int ji = pj[i];
        int rank = 0;
        for (int k = 0; k < n; k++) {
            float dk = pd[k]; int jk = pj[k];
            rank += (dk < di || (dk == di && jk < ji)) ? 1 : 0;
        }
        if (rank < KNN) {
            g_eidx[(size_t)row*KNN + rank] = ji;
            g_dnb [(size_t)row*KNN + rank] = di;
            out[EI_OFF + (size_t)row*KNN + rank] = (float)ji;
        }
    }
}

// ---------------- Edge: features + GEMM(400->128, W via L1/L2) + Tpos + LN ----------------
#define EFEAT_ROWS 144
#define EDGE_SMF (EFEAT_ROWS*64 + 32 + 960 + 64 + 64 + 64)   // 10400 floats = 41.6KB
__global__ __launch_bounds__(256, 3) void k_edge(
    const int* __restrict__ R_idx, const int* __restrict__ chains,
    const float* __restrict__ b_edge, const float* __restrict__ g_edge,
    const float* __restrict__ be_edge, float* __restrict__ out) {
    extern __shared__ float sm[];
    float* feats = sm;                       // [144][64]
    float* ai    = sm + EFEAT_ROWS*64;       // 32
    float* aj    = ai + 32;                  // [64][15]
    float* dnb   = aj + 960;                 // 64
    int*   sJ    = (int*)(dnb + 64);         // 64
    int*   sdc   = sJ + 64;                  // 64

    int t = threadIdx.x;
    int r0 = blockIdx.x * 2;
    int b  = r0 >> 11;
    int ebase = blockIdx.x * 64;
    int lane = t & 31, w = t >> 5;

    if (t < 30) ai[t] = g_atoms[r0*15 + t];
    if (t < 64) { sJ[t] = g_eidx[ebase + t]; dnb[t] = g_dnb[ebase + t]; }
    __syncthreads();
    for (int k = t; k < 960; k += 256) {
        int e = k / 15, c = k % 15;
        aj[k] = g_atoms[(size_t)(b*LLEN + sJ[e])*15 + c];
    }
    if (t < 64) {
        int ig = r0 + (t >> 5);
        int jg = b*LLEN + sJ[t];
        int off = R_idx[ig] - R_idx[jg];
        int ec  = (chains[ig] == chains[jg]);
        int d = off + 32; d = d < 0 ? 0 : (d > 64 ? 64 : d);
        sdc[t] = ec ? d : 65;
    }
    __syncthreads();

    ull acc[16];
    {
        float4 b4 = ((const float4*)b_edge)[lane];
        ull b0 = pack2(b4.x), b1 = pack2(b4.y), b2 = pack2(b4.z), b3 = pack2(b4.w);
#pragma unroll
        for (int p = 0; p < 4; p++) { acc[p*4]=b0; acc[p*4+1]=b1; acc[p*4+2]=b2; acc[p*4+3]=b3; }
    }

    int pbase = 0;
    for (int ph = 0; ph < 3; ph++) {
        int P = ph ? 8 : 9;
        {
            int e = t & 63, psub = t >> 6;
            const float* A  = ai + (e >> 5) * 15;
            const float* Bv = aj + e * 15;
            for (int p = psub; p < P; p += 4) {
                int gp = pbase + p;
                float D;
                if (gp == 0) D = dnb[e];
                else {
                    int pa = c_PA24[gp-1]*3, pb = c_PB24[gp-1]*3;
                    float dx=A[pa]-Bv[pb], dy=A[pa+1]-Bv[pb+1], dz=A[pa+2]-Bv[pb+2];
                    D = sqrtf(dx*dx + dy*dy + dz*dz + 1e-6f);
                }
                rbf16(D, &feats[(p*16)*64 + e], 64);
            }
        }
        __syncthreads();                 // feats ready for this phase
        for (int kc = 0; kc < P; kc++) {
            const float4* Wg = (const float4*)g_WeT + (size_t)(pbase+kc+1)*512 + lane;
            const float* fb = feats + (kc*16)*64 + 8*w;
#pragma unroll
            for (int fi = 0; fi < 16; fi++) {
                float4 w4 = __ldg(&Wg[fi*32]);
                ulonglong2 f01 = *(const ulonglong2*)&fb[fi*64];
                ulonglong2 f23 = *(const ulonglong2*)&fb[fi*64 + 4];
                ull w0 = pack2(w4.x), w1 = pack2(w4.y), w2 = pack2(w4.z), w3 = pack2(w4.w);
                ffma2(acc[0],  f01.x, w0); ffma2(acc[1],  f01.x, w1);
                ffma2(acc[2],  f01.x, w2); ffma2(acc[3],  f01.x, w3);
                ffma2(acc[4],  f01.y, w0); ffma2(acc[5],  f01.y, w1);
                ffma2(acc[6],  f01.y, w2); ffma2(acc[7],  f01.y, w3);
                ffma2(acc[8],  f23.x, w0); ffma2(acc[9],  f23.x, w1);
                ffma2(acc[10], f23.x, w2); ffma2(acc[11], f23.x, w3);
                ffma2(acc[12], f23.y, w0); ffma2(acc[13], f23.y, w1);
                ffma2(acc[14], f23.y, w2); ffma2(acc[15], f23.y, w3);
            }
        }
        __syncthreads();                 // protect feats before next phase writes
        pbase += P;
    }

    float4 g4  = ((const float4*)g_edge)[lane];
    float4 be4 = ((const float4*)be_edge)[lane];
    float4* o4 = (float4*)(out + E_OFF);
#pragma unroll
    for (int p = 0; p < 4; p++) {
        float2 u0 = unpack2(acc[p*4]);
        float2 u1 = unpack2(acc[p*4+1]);
        float2 u2 = unpack2(acc[p*4+2]);
        float2 u3 = unpack2(acc[p*4+3]);
        int e0 = 8*w + 2*p, e1 = e0 + 1;
        float4 tp0 = ((const float4*)g_Tpos)[sdc[e0]*32 + lane];
        float4 tp1 = ((const float4*)g_Tpos)[sdc[e1]*32 + lane];
        float4 a0 = make_float4(u0.x+tp0.x, u1.x+tp0.y, u2.x+tp0.z, u3.x+tp0.w);
        float4 a1 = make_float4(u0.y+tp1.x, u1.y+tp1.y, u2.y+tp1.z, u3.y+tp1.w);
        float4 r0v = ln128(a0, g4, be4);
        float4 r1v = ln128(a1, g4, be4);
        o4[(size_t)(ebase+e0)*32 + lane] = r0v;
        o4[(size_t)(ebase+e1)*32 + lane] = r1v;
    }
}

// ---------------- V node: features + GEMM(96->128, W via L1/L2) + fuse + LN ----------------
#define VN_SMF (96*64 + 64 + 192 + 36 + 192)   // 6628 floats = 26.5KB
__global__ __launch_bounds__(256, 3) void k_vnode(
    const float* __restrict__ Y, const int* __restrict__ Y_t, const int* __restrict__ pt,
    const float* __restrict__ g_node, const float* __restrict__ bn_node,
    float* __restrict__ out) {
    extern __shared__ float sm[];
    float* feats = sm;                    // [96][64]
    float* at    = sm + 96*64;            // [4][15] pad 64
    float* ys    = at + 64;               // [64][3]
    float* fr    = ys + 192;              // [4][9]
    int*   cols  = (int*)(fr + 36);       // [64][3]

    int t = threadIdx.x;
    int bid = blockIdx.x;
    int rbase = bid * 4;
    int rowg0 = bid * 64;
    int lane = t & 31, w = t >> 5;

    if (t < 60) at[t] = g_atoms[(size_t)rbase*15 + t];
    if (t < 192) ys[t] = Y[(size_t)rowg0*3 + t];
    if (t < 64) {
        int yt = Y_t[rowg0 + t];
        cols[t*3+0] = yt;
        cols[t*3+1] = 120 + pt[120 + yt];
        cols[t*3+2] = 139 + pt[240 + yt];
    }
    for (int idx = t; idx < 12*64; idx += 256) feats[84*64 + idx] = 0.0f;
    __syncthreads();
    if (t < 4) {
        const float* A = at + t*15;
        float v1x=A[0]-A[3], v1y=A[1]-A[4], v1z=A[2]-A[5];
        float v2x=A[6]-A[3], v2y=A[7]-A[4], v2z=A[8]-A[5];
        float n1 = sqrtf(v1x*v1x+v1y*v1y+v1z*v1z) + 1e-8f;
        float e1x=v1x/n1, e1y=v1y/n1, e1z=v1z/n1;
        float d12 = e1x*v2x + e1y*v2y + e1z*v2z;
        float ux=v2x-e1x*d12, uy=v2y-e1y*d12, uz=v2z-e1z*d12;
        float n2 = sqrtf(ux*ux+uy*uy+uz*uz) + 1e-8f;
        float e2x=ux/n2, e2y=uy/n2, e2z=uz/n2;
        float e3x=e1y*e2z-e1z*e2y, e3y=e1z*e2x-e1x*e2z, e3z=e1x*e2y-e1y*e2x;
        float* F = fr + t*9;
        F[0]=e1x;F[1]=e1y;F[2]=e1z; F[3]=e2x;F[4]=e2y;F[5]=e2z; F[6]=e3x;F[7]=e3y;F[8]=e3z;
    }
    {
        int row = t & 63, res = row >> 4;
        const float* yy = ys + row*3;
        for (int p = t >> 6; p < 5; p += 4) {
            const float* A = at + res*15 + p*3;
            float dx=A[0]-yy[0], dy=A[1]-yy[1], dz=A[2]-yy[2];
            float D = sqrtf(dx*dx+dy*dy+dz*dz + 1e-6f);
            rbf16(D, &feats[(p*16)*64 + row], 64);
        }
    }
    __syncthreads();
    if (t < 64) {
        int row = t, res = row >> 4;
        const float* F = fr + res*9;
        float dx = ys[row*3]   - at[res*15+3];
        float dy = ys[row*3+1] - at[res*15+4];
        float dz = ys[row*3+2] - at[res*15+5];
        float lv0 = F[0]*dx+F[1]*dy+F[2]*dz;
        float lv1 = F[3]*dx+F[4]*dy+F[5]*dz;
        float lv2 = F[6]*dx+F[7]*dy+F[8]*dz;
        float rxy  = sqrtf(lv0*lv0 + lv1*lv1 + 1e-8f);
        float rxyz = sqrtf(lv0*lv0 + lv1*lv1 + lv2*lv2) + 1e-8f;
        feats[80*64+row] = lv0/rxy;
        feats[81*64+row] = lv1/rxy;
        feats[82*64+row] = rxy/rxyz;
        feats[83*64+row] = lv2/rxyz;
    }
    __syncthreads();
    ull acc[16];
    {
        float4 b4 = ((const float4*)g_btf)[lane];
        ull b0 = pack2(b4.x), b1 = pack2(b4.y), b2 = pack2(b4.z), b3 = pack2(b4.w);
#pragma unroll
        for (int p = 0; p < 4; p++) { acc[p*4]=b0; acc[p*4+1]=b1; acc[p*4+2]=b2; acc[p*4+3]=b3; }
    }
    for (int kc = 0; kc < 6; kc++) {
        const float4* Wg = (const float4*)g_WdT2 + (size_t)kc*512 + lane;
        const float* fb = feats + (kc*16)*64 + 8*w;
#pragma unroll
        for (int fi = 0; fi < 16; fi++) {
            float4 w4 = __ldg(&Wg[fi*32]);
            ulonglong2 f01 = *(const ulonglong2*)&fb[fi*64];
            ulonglong2 f23 = *(const ulonglong2*)&fb[fi*64 + 4];
            ull w0 = pack2(w4.x), w1 = pack2(w4.y), w2 = pack2(w4.z), w3 = pack2(w4.w);
            ffma2(acc[0],  f01.x, w0); ffma2(acc[1],  f01.x, w1);
            ffma2(acc[2],  f01.x, w2); ffma2(acc[3],  f01.x, w3);
            ffma2(acc[4],  f01.y, w0); ffma2(acc[5],  f01.y, w1);
            ffma2(acc[6],  f01.y, w2); ffma2(acc[7],  f01.y, w3);
            ffma2(acc[8],  f23.x, w0); ffma2(acc[9],  f23.x, w1);
            ffma2(acc[10], f23.x, w2); ffma2(acc[11], f23.x, w3);
            ffma2(acc[12], f23.y, w0); ffma2(acc[13], f23.y, w1);
            ffma2(acc[14], f23.y, w2); ffma2(acc[15], f23.y, w3);
        }
    }
    float4 g4  = ((const float4*)g_node)[lane];
    float4 be4 = ((const float4*)bn_node)[lane];
    float4* o4 = (float4*)(out + V_OFF);
#pragma unroll
    for (int p = 0; p < 4; p++) {
        float2 u0 = unpack2(acc[p*4]);
        float2 u1 = unpack2(acc[p*4+1]);
        float2 u2 = unpack2(acc[p*4+2]);
        float2 u3 = unpack2(acc[p*4+3]);
        int e0 = 8*w + 2*p, e1 = e0 + 1;
        float4 a0 = make_float4(u0.x, u1.x, u2.x, u3.x);
        float4 a1 = make_float4(u0.y, u1.y, u2.y, u3.y);
#pragma unroll
        for (int j = 0; j < 3; j++) {
            float4 q0 = ((const float4*)g_Wfuse)[cols[e0*3+j]*32 + lane];
            float4 q1 = ((const float4*)g_Wfuse)[cols[e1*3+j]*32 + lane];
            a0.x+=q0.x; a0.y+=q0.y; a0.z+=q0.z; a0.w+=q0.w;
            a1.x+=q1.x; a1.y+=q1.y; a1.z+=q1.z; a1.w+=q1.w;
        }
        float4 r0v = ln128(a0, g4, be4);
        float4 r1v = ln128(a1, g4, be4);
        o4[(size_t)(rowg0+e0)*32 + lane] = r0v;
        o4[(size_t)(rowg0+e1)*32 + lane] = r1v;
    }
}

// ---------------- Y_nodes (gather + LN) + Y_m copy ----------------
__global__ __launch_bounds__(256) void k_ynode(
    const float* __restrict__ Y_m, const int* __restrict__ Y_t, const int* __restrict__ pt,
    const float* __restrict__ b_yn, const float* __restrict__ g_yn,
    const float* __restrict__ bn_yn, float* __restrict__ out) {
    int t = threadIdx.x, lane = t & 31, w = t >> 5;
    int row = blockIdx.x*8 + w;
    int yt = Y_t[row];
    int c0 = yt, c1 = 120 + pt[120+yt], c2 = 139 + pt[240+yt];
    float4 a  = ((const float4*)&g_WynT[(size_t)c0*128])[lane];
    float4 a1 = ((const float4*)&g_WynT[(size_t)c1*128])[lane];
    float4 a2 = ((const float4*)&g_WynT[(size_t)c2*128])[lane];
    float4 b4 = ((const float4*)b_yn)[lane];
    a.x += a1.x + a2.x + b4.x;
    a.y += a1.y + a2.y + b4.y;
    a.z += a1.z + a2.z + b4.z;
    a.w += a1.w + a2.w + b4.w;
    float4 g4  = ((const float4*)g_yn)[lane];
    float4 be4 = ((const float4*)bn_yn)[lane];
    float4 r = ln128(a, g4, be4);
    ((float4*)(out + YN_OFF))[(size_t)row*32 + lane] = r;
    if (lane == 0) out[YM_OFF + row] = Y_m[row];
}

// ---------------- Y_edges: symmetric pairs, 16->128 + LN ----------------
__global__ __launch_bounds__(256) void k_yedge(
    const float* __restrict__ Y, const float* __restrict__ W_ye,
    const float* __restrict__ b_ye, const float* __restrict__ g_ye,
    const float* __restrict__ bn_ye, float* __restrict__ out) {
    __shared__ float ys[48];
    __shared__ float rbfs[136*16];
    __shared__ float WyeS[16*128];
    __shared__ int sm1[136], sm2[136];
    int t = threadIdx.x, bl = blockIdx.x;
    if (t < 48) ys[t] = Y[(size_t)bl*48 + t];
    for (int i = t; i < 2048; i += 256) {
        int c = i >> 4, r = i & 15;
        WyeS[r*128 + c] = W_ye[i];
    }
    if (t < 136) {
        int u = t, m1 = 0;
        while (u >= 16 - m1) { u -= 16 - m1; m1++; }
        sm1[t] = m1; sm2[t] = m1 + u;
    }
    __syncthreads();
    if (t < 136) {
        int m1 = sm1[t], m2 = sm2[t];
        float dx = ys[m1*3]-ys[m2*3], dy = ys[m1*3+1]-ys[m2*3+1], dz = ys[m1*3+2]-ys[m2*3+2];
        float D = sqrtf(dx*dx + dy*dy + dz*dz + 1e-6f);
        rbf16(D, &rbfs[t*16], 1);
    }
    __syncthreads();
    int lane = t & 31, w = t >> 5;
    float4 bye4 = ((const float4*)b_ye)[lane];
    float4 g4   = ((const float4*)g_ye)[lane];
    float4 be4  = ((const float4*)bn_ye)[lane];
    float4* o4 = (float4*)out;
    size_t yebase4 = YE_OFF >> 2;
    for (int u = w; u < 136; u += 8) {
        float4 a = bye4;
#pragma unroll
        for (int r = 0; r < 16; r++) {
            float rb = rbfs[u*16 + r];
            float4 wv = ((const float4*)&WyeS[r*128])[lane];
            a.x = fmaf(rb, wv.x, a.x); a.y = fmaf(rb, wv.y, a.y);
            a.z = fmaf(rb, wv.z, a.z); a.w = fmaf(rb, wv.w, a.w);
        }
        float4 res = ln128(a, g4, be4);
        int m1 = sm1[u], m2 = sm2[u];
        size_t r1 = (size_t)bl*256 + m1*16 + m2;
        size_t r2 = (size_t)bl*256 + m2*16 + m1;
        o4[yebase4 + r1*32 + lane] = res;
        if (r2 != r1) o4[yebase4 + r2*32 + lane] = res;
    }
}

// ---------------- launch: multi-stream DAG; yedge overlapped with edge ----------------
extern "C" void kernel_launch(void* const* d_in, const int* in_sizes, int n_in,
                              void* d_out, int out_size) {
    const float* X        = (const float*)d_in[0];
    const float* Y        = (const float*)d_in[1];
    const float* Y_m      = (const float*)d_in[2];
    const float* mask     = (const float*)d_in[3];
    const float* W_pos    = (const float*)d_in[4];
    const float* b_pos    = (const float*)d_in[5];
    const float* W_edge   = (const float*)d_in[6];
    const float* b_edge   = (const float*)d_in[7];
    const float* g_edge   = (const float*)d_in[8];
    const float* be_edge  = (const float*)d_in[9];
    const float* W_down   = (const float*)d_in[10];
    const float* b_down   = (const float*)d_in[11];
    const float* g_node   = (const float*)d_in[12];
    const float* bn_node  = (const float*)d_in[13];
    const float* W_type   = (const float*)d_in[14];
    const float* b_type   = (const float*)d_in[15];
    const float* W_yn     = (const float*)d_in[16];
    const float* b_yn     = (const float*)d_in[17];
    const float* g_yn     = (const float*)d_in[18];
    const float* bn_yn    = (const float*)d_in[19];
    const float* W_ye     = (const float*)d_in[20];
    const float* b_ye     = (const float*)d_in[21];
    const float* g_ye     = (const float*)d_in[22];
    const float* bn_ye    = (const float*)d_in[23];
    const int*   Y_t      = (const int*)d_in[24];
    const int*   R_idx    = (const int*)d_in[25];
    const int*   chains   = (const int*)d_in[26];
    const int*   pt       = (const int*)d_in[27];
    float* out = (float*)d_out;

    static bool init_done = false;
    static cudaStream_t s2, s3;
    static cudaEvent_t evRoot, evAtoms, evTF, evTopk, evS2, evS3;
    if (!init_done) {
        cudaStreamCreateWithFlags(&s2, cudaStreamNonBlocking);
        cudaStreamCreateWithFlags(&s3, cudaStreamNonBlocking);
        cudaEventCreateWithFlags(&evRoot,  cudaEventDisableTiming);
        cudaEventCreateWithFlags(&evAtoms, cudaEventDisableTiming);
        cudaEventCreateWithFlags(&evTF,    cudaEventDisableTiming);
        cudaEventCreateWithFlags(&evTopk,  cudaEventDisableTiming);
        cudaEventCreateWithFlags(&evS2,    cudaEventDisableTiming);
        cudaEventCreateWithFlags(&evS3,    cudaEventDisableTiming);
        cudaFuncSetAttribute(k_edge,  cudaFuncAttributeMaxDynamicSharedMemorySize, EDGE_SMF*4);
        cudaFuncSetAttribute(k_vnode, cudaFuncAttributeMaxDynamicSharedMemorySize, VN_SMF*4);
        init_done = true;
    }

    // fork from origin stream
    cudaEventRecord(evRoot, 0);
    cudaStreamWaitEvent(s2, evRoot, 0);
    cudaStreamWaitEvent(s3, evRoot, 0);

    // s2: weight prep chain + ynode (runs concurrent with topk)
    k_trans<<<(416*128 + 148*128 + 96*128 + 147*128 + 255)/256, 256, 0, s2>>>(W_edge, W_down, W_yn);
    k_fuse<<<(66*128 + 147*128 + 128 + 255)/256, 256, 0, s2>>>(W_pos, b_pos, W_edge, W_type, b_type, b_down);
    cudaEventRecord(evTF, s2);
    k_ynode<<<NROW/8, 256, 0, s2>>>(Y_m, Y_t, pt, b_yn, g_yn, bn_yn, out);

    // s0: geometry chain
    k_atoms<<<NRES/256, 256>>>(X);
    cudaEventRecord(evAtoms, 0);

    // s2: vnode needs atoms + trans + fuse (runs concurrent with topk/edge)
    cudaStreamWaitEvent(s2, evAtoms, 0);
    k_vnode<<<NROW/64, 256, VN_SMF*4, s2>>>(Y, Y_t, pt, g_node, bn_node, out);
    cudaEventRecord(evS2, s2);

    // s0: topk then edge (edge also needs trans+fuse)
    k_topk<<<NRES, 256, 0, 0>>>(mask, out);
    cudaEventRecord(evTopk, 0);
    cudaStreamWaitEvent(0, evTF, 0);
    k_edge<<<NEDGE/64, 256, EDGE_SMF*4, 0>>>(R_idx, chains, b_edge, g_edge, be_edge, out);

    // s3: yedge delayed to co-run with edge (DRAM-bound vs FMA-bound)
    cudaStreamWaitEvent(s3, evTopk, 0);
    k_yedge<<<BB*LLEN, 256, 0, s3>>>(Y, W_ye, b_ye, g_ye, bn_ye, out);
    cudaEventRecord(evS3, s3);

    // join
    cudaStreamWaitEvent(0, evS2, 0);
    cudaStreamWaitEvent(0, evS3, 0);
}

// round 16
// speedup vs baseline: 1.6324x; 1.0003x over previous
#include <cuda_runtime.h>
#include <cuda_bf16.h>

#define BB 2
#define LLEN 2048
#define MM 16
#define KNN 32
#define NRES (BB*LLEN)            // 4096
#define NEDGE (NRES*KNN)          // 131072
#define NROW (NRES*MM)            // 65536

static const size_t V_OFF  = 0;
static const size_t E_OFF  = (size_t)NROW*128;                  // 8388608
static const size_t EI_OFF = E_OFF + (size_t)NEDGE*128;         // 25165824
static const size_t YN_OFF = EI_OFF + (size_t)NEDGE;            // 25296896
static const size_t YE_OFF = YN_OFF + (size_t)NROW*128;         // 33685504
static const size_t YM_OFF = YE_OFF + (size_t)NRES*MM*MM*128;   // 167903232

typedef unsigned long long ull;

// ---------------- device scratch ----------------
__device__ float g_atoms[NRES*15];
__device__ float g_cax[NRES*3];
__device__ int   g_eidx[NEDGE];
__device__ float g_dnb[NEDGE];
__device__ float g_WeT[416*128];      // W_edge^T [f][n]
__device__ float g_WdTF[148*128];     // W_down^T full [f][n]
__device__ float g_WdT2[96*128];      // compact rows
__device__ float g_WynT[147*128];     // W_yn^T [f][c]
__device__ float g_Tpos[66*128];      // fused pos table
__device__ float g_Wfuse[147*128];    // Wt^T . Wd[:,80:144]^T
__device__ float g_btf[128];          // fused bias

// pairs (excluding leading D_neighbors block); atoms: N=0,Ca=1,C=2,O=3,Cb=4
__constant__ int c_PA24[24] = {0,2,3,4, 1,1,1,1, 0,0,0, 4,4, 3, 0,2,3,4, 2,3,4, 2,3, 2};
__constant__ int c_PB24[24] = {0,2,3,4, 0,2,3,4, 2,3,4, 2,3, 2, 1,1,1,1, 0,0,0, 4,4, 3};

// ---------------- f32x2 helpers ----------------
__device__ __forceinline__ ull pack2(float s) {
    ull r; asm("mov.b64 %0, {%1, %1};" : "=l"(r) : "r"(__float_as_uint(s))); return r;
}
__device__ __forceinline__ void ffma2(ull& a, ull s, ull w) {
    asm("fma.rn.f32x2 %0, %1, %2, %0;" : "+l"(a) : "l"(s), "l"(w));
}
__device__ __forceinline__ float2 unpack2(ull a) {
    unsigned lo, hi; asm("mov.b64 {%0, %1}, %2;" : "=r"(lo), "=r"(hi) : "l"(a));
    return make_float2(__uint_as_float(lo), __uint_as_float(hi));
}
__device__ __forceinline__ float4 ln128(float4 a, float4 g, float4 be) {
    float s  = a.x + a.y + a.z + a.w;
    float ss = fmaf(a.x,a.x, fmaf(a.y,a.y, fmaf(a.z,a.z, a.w*a.w)));
#pragma unroll
    for (int o = 16; o; o >>= 1) {
        s  += __shfl_xor_sync(0xffffffffu, s,  o);
        ss += __shfl_xor_sync(0xffffffffu, ss, o);
    }
    float mu   = s * 0.0078125f;
    float var  = ss * 0.0078125f - mu*mu;
    float rstd = rsqrtf(var + 1e-5f);
    float4 o4;
    o4.x = (a.x-mu)*rstd*g.x + be.x;
    o4.y = (a.y-mu)*rstd*g.y + be.y;
    o4.z = (a.z-mu)*rstd*g.z + be.z;
    o4.w = (a.w-mu)*rstd*g.w + be.w;
    return o4;
}

// 16 RBF values with 3 exps: anchor at nearest mu, geometric ratio chain.
// decay = exp(-2*DLT^2/sigma^2) hardcoded (compile-time constant).
__device__ __forceinline__ void rbf16(float D, float* dst, int stride) {
    const float DLT = 1.3333333333333333f;
    const float IS2 = 0.64f;
    const float C1  = 1.7066666666666668f;
    const float C2  = 1.1377777777777778f;
    const float DECAY = 0.102796935f;      // exp(-2*C2), hardcoded (was a 4th __expf)
    float u = (D - 2.0f) * 0.75f;
    int rs = __float2int_rn(u);
    rs = rs < 0 ? 0 : (rs > 15 ? 15 : rs);
    float x = D - (2.0f + DLT * (float)rs);
    float peak  = __expf(-x*x*IS2);
    float fup   = __expf( C1*x - C2);
    float fdn   = __expf(-C1*x - C2);
    float v = peak;
    dst[rs*stride] = v;
    float f = fup;
    for (int r = rs+1; r < 16; r++) { v *= f; dst[r*stride] = v; f *= DECAY; }
    v = peak; f = fdn;
    for (int r = rs-1; r >= 0; r--) { v *= f; dst[r*stride] = v; f *= DECAY; }
}

// ---------------- prep kernels ----------------
__global__ void k_atoms(const float* __restrict__ X) {
    int r = blockIdx.x*blockDim.x + threadIdx.x;
    if (r >= NRES) return;
    const float* x = X + (size_t)r*12;
    float nx=x[0],ny=x[1],nz=x[2], cax=x[3],cay=x[4],caz=x[5];
    float cxx=x[6],cyy=x[7],czz=x[8], ox=x[9],oy=x[10],oz=x[11];
    float bx=cax-nx, by=cay-ny, bz=caz-nz;
    float ccx=cxx-cax, ccy=cyy-cay, ccz=czz-caz;
    float ax=by*ccz-bz*ccy, ay=bz*ccx-bx*ccz, az=bx*ccy-by*ccx;
    float cbx=-0.58273431f*ax+0.56802827f*bx-0.54067466f*ccx+cax;
    float cby=-0.58273431f*ay+0.56802827f*by-0.54067466f*ccy+cay;
    float cbz=-0.58273431f*az+0.56802827f*bz-0.54067466f*ccz+caz;
    float* o = g_atoms + (size_t)r*15;
    o[0]=nx;o[1]=ny;o[2]=nz; o[3]=cax;o[4]=cay;o[5]=caz;
    o[6]=cxx;o[7]=cyy;o[8]=czz; o[9]=ox;o[10]=oy;o[11]=oz;
    o[12]=cbx;o[13]=cby;o[14]=cbz;
    g_cax[r*3+0]=cax; g_cax[r*3+1]=cay; g_cax[r*3+2]=caz;
}

__global__ void k_trans(const float* __restrict__ We, const float* __restrict__ Wd,
                        const float* __restrict__ Wyn) {
    int i = blockIdx.x*blockDim.x + threadIdx.x;
    if (i < 416*128) { int f=i>>7, n=i&127; g_WeT[i] = We[n*416+f]; return; }
    i -= 416*128;
    if (i < 148*128) { int f=i>>7, n=i&127; g_WdTF[i] = Wd[n*148+f]; return; }
    i -= 148*128;
    if (i < 96*128) {
        int f=i>>7, n=i&127;
        float v = 0.0f;
        if (f < 80) v = Wd[n*148+f];
        else if (f < 84) v = Wd[n*148+144+(f-80)];
        g_WdT2[i] = v; return;
    }
    i -= 96*128;
    if (i < 147*128) { int f=i>>7, c=i&127; g_WynT[i] = Wyn[c*147+f]; }
}

__global__ void k_fuse(const float* __restrict__ Wp, const float* __restrict__ bp,
                       const float* __restrict__ We, const float* __restrict__ Wt,
                       const float* __restrict__ bt, const float* __restrict__ bd) {
    int i = blockIdx.x*blockDim.x + threadIdx.x;
    if (i < 66*128) {
        int d = i>>7, n = i&127;
        float s = 0.0f;
        for (int c = 0; c < 16; c++) s = fmaf(Wp[c*66+d] + bp[c], We[n*416+c], s);
        g_Tpos[i] = s; return;
    }
    i -= 66*128;
    if (i < 147*128) {
        int f = i>>7, n = i&127;
        float s = 0.0f;
        for (int c = 0; c < 64; c++) s = fmaf(Wt[c*147+f], g_WdTF[(80+c)*128+n], s);
        g_Wfuse[i] = s; return;
    }
    i -= 147*128;
    if (i < 128) {
        float s = bd[i];
        for (int c = 0; c < 64; c++) s = fmaf(bt[c], g_WdTF[(80+c)*128+i], s);
        g_btf[i] = s;
    }
}

// ---------------- top-K neighbors: histogram pre-filter + parallel rank selection ----------------
__global__ __launch_bounds__(256) void k_topk(const float* __restrict__ mask,
                                              float* __restrict__ out) {
    int row = blockIdx.x, b = row >> 11, t = threadIdx.x;
    int lane = t & 31, w = t >> 5;
    __shared__ float smax[8];
    __shared__ unsigned hist[256];
    __shared__ float pd[2048];
    __shared__ int   pj[2048];
    __shared__ int   scnt;
    __shared__ int   sthr;

    hist[t] = 0u;
    if (t == 0) scnt = 0;

    float cx = g_cax[row*3], cy = g_cax[row*3+1], cz = g_cax[row*3+2];
    float mi = mask[row];
    float dv[8], m2v[8];
    float lmax = -1e30f;
#pragma unroll
    for (int q = 0; q < 8; q++) {
        int jr = b*LLEN + t + (q<<8);
        float dx = cx - g_cax[jr*3], dy = cy - g_cax[jr*3+1], dz = cz - g_cax[jr*3+2];
        float dist = sqrtf(dx*dx + dy*dy + dz*dz + 1e-6f);
        float m2 = mi * mask[jr];
        dv[q] = m2 * dist; m2v[q] = m2;
        lmax = fmaxf(lmax, dv[q]);
    }
#pragma unroll
    for (int o = 16; o; o >>= 1) lmax = fmaxf(lmax, __shfl_xor_sync(0xffffffffu, lmax, o));
    if (lane == 0) smax[w] = lmax;
    __syncthreads();
    float dmax = fmaxf(fmaxf(fmaxf(smax[0],smax[1]),fmaxf(smax[2],smax[3])),
                       fmaxf(fmaxf(smax[4],smax[5]),fmaxf(smax[6],smax[7])));
    float inv = 256.0f / (dmax + 1e-6f);
#pragma unroll
    for (int q = 0; q < 8; q++) {
        dv[q] += (1.0f - m2v[q]) * dmax;
        int bq = (int)(dv[q] * inv);
        bq = bq < 0 ? 0 : (bq > 255 ? 255 : bq);
        atomicAdd(&hist[bq], 1u);
    }
    __syncthreads();

    if (w == 0) {
        unsigned s = 0;
#pragma unroll
        for (int k = 0; k < 8; k++) s += hist[lane*8 + k];
        unsigned scan = s;
#pragma unroll
        for (int o = 1; o < 32; o <<= 1) {
            unsigned v = __shfl_up_sync(0xffffffffu, scan, o);
            if (lane >= o) scan += v;
        }
        unsigned ballot = __ballot_sync(0xffffffffu, scan >= KNN);
        int fl = __ffs(ballot) - 1;
        if (lane == fl) {
            unsigned cum = scan - s;
            int bt_ = lane*8;
            for (int k = 0; k < 8; k++) {
                cum += hist[lane*8 + k];
                if (cum >= KNN) { bt_ = lane*8 + k; break; }
            }
            sthr = bt_;
        }
    }
    __syncthreads();

    int thr = sthr;
#pragma unroll
    for (int q = 0; q < 8; q++) {
        int bq = (int)(dv[q] * inv);
        bq = bq < 0 ? 0 : (bq > 255 ? 255 : bq);
        if (bq <= thr) {
            int p = atomicAdd(&scnt, 1);
            pd[p] = dv[q];
            pj[p] = t + (q<<8);
        }
    }
    __syncthreads();

    // parallel exact rank-by-counting over the compacted superset
    int n = scnt;
    for (int i = t; i < n; i += 256) {
        float di = pd[i]; int ji = pj[i];
        int rank = 0;
        for (int k = 0; k < n; k++) {
            float dk = pd[k]; int jk = pj[k];
            rank += (dk < di || (dk == di && jk < ji)) ? 1 : 0;
        }
        if (rank < KNN) {
            g_eidx[(size_t)row*KNN + rank] = ji;
            g_dnb [(size_t)row*KNN + rank] = di;
            out[EI_OFF + (size_t)row*KNN + rank] = (float)ji;
        }
    }
}

// ---------------- Edge: features + GEMM(400->128, W via L1/L2) + Tpos + LN ----------------
#define EFEAT_ROWS 144
#define EDGE_SMF (EFEAT_ROWS*64 + 32 + 960 + 64 + 64 + 64)   // 10400 floats = 41.6KB
__global__ __launch_bounds__(256, 3) void k_edge(
    const int* __restrict__ R_idx, const int* __restrict__ chains,
    const float* __restrict__ b_edge, const float* __restrict__ g_edge,
    const float* __restrict__ be_edge, float* __restrict__ out) {
    extern __shared__ float sm[];
    float* feats = sm;                       // [144][64]
    float* ai    = sm + EFEAT_ROWS*64;       // 32
    float* aj    = ai + 32;                  // [64][15]
    float* dnb   = aj + 960;                 // 64
    int*   sJ    = (int*)(dnb + 64);         // 64
    int*   sdc   = sJ + 64;                  // 64

    int t = threadIdx.x;
    int r0 = blockIdx.x * 2;
    int b  = r0 >> 11;
    int ebase = blockIdx.x * 64;
    int lane = t & 31, w = t >> 5;

    if (t < 30) ai[t] = g_atoms[r0*15 + t];
    if (t < 64) { sJ[t] = g_eidx[ebase + t]; dnb[t] = g_dnb[ebase + t]; }
    __syncthreads();
    for (int k = t; k < 960; k += 256) {
        int e = k / 15, c = k % 15;
        aj[k] = g_atoms[(size_t)(b*LLEN + sJ[e])*15 + c];
    }
    if (t < 64) {
        int ig = r0 + (t >> 5);
        int jg = b*LLEN + sJ[t];
        int off = R_idx[ig] - R_idx[jg];
        int ec  = (chains[ig] == chains[jg]);
        int d = off + 32; d = d < 0 ? 0 : (d > 64 ? 64 : d);
        sdc[t] = ec ? d : 65;
    }
    __syncthreads();

    ull acc[16];
    {
        float4 b4 = ((const float4*)b_edge)[lane];
        ull b0 = pack2(b4.x), b1 = pack2(b4.y), b2 = pack2(b4.z), b3 = pack2(b4.w);
#pragma unroll
        for (int p = 0; p < 4; p++) { acc[p*4]=b0; acc[p*4+1]=b1; acc[p*4+2]=b2; acc[p*4+3]=b3; }
    }

    int pbase = 0;
    for (int ph = 0; ph < 3; ph++) {
        int P = ph ? 8 : 9;
        {
            int e = t & 63, psub = t >> 6;
            const float* A  = ai + (e >> 5) * 15;
            const float* Bv = aj + e * 15;
            for (int p = psub; p < P; p += 4) {
                int gp = pbase + p;
                float D;
                if (gp == 0) D = dnb[e];
                else {
                    int pa = c_PA24[gp-1]*3, pb = c_PB24[gp-1]*3;
                    float dx=A[pa]-Bv[pb], dy=A[pa+1]-Bv[pb+1], dz=A[pa+2]-Bv[pb+2];
                    D = sqrtf(dx*dx + dy*dy + dz*dz + 1e-6f);
                }
                rbf16(D, &feats[(p*16)*64 + e], 64);
            }
        }
        __syncthreads();                 // feats ready for this phase
        for (int kc = 0; kc < P; kc++) {
            const float4* Wg = (const float4*)g_WeT + (size_t)(pbase+kc+1)*512 + lane;
            const float* fb = feats + (kc*16)*64 + 8*w;
#pragma unroll
            for (int fi = 0; fi < 16; fi++) {
                float4 w4 = __ldg(&Wg[fi*32]);
                ulonglong2 f01 = *(const ulonglong2*)&fb[fi*64];
                ulonglong2 f23 = *(const ulonglong2*)&fb[fi*64 + 4];
                ull w0 = pack2(w4.x), w1 = pack2(w4.y), w2 = pack2(w4.z), w3 = pack2(w4.w);
                ffma2(acc[0],  f01.x, w0); ffma2(acc[1],  f01.x, w1);
                ffma2(acc[2],  f01.x, w2); ffma2(acc[3],  f01.x, w3);
                ffma2(acc[4],  f01.y, w0); ffma2(acc[5],  f01.y, w1);
                ffma2(acc[6],  f01.y, w2); ffma2(acc[7],  f01.y, w3);
                ffma2(acc[8],  f23.x, w0); ffma2(acc[9],  f23.x, w1);
                ffma2(acc[10], f23.x, w2); ffma2(acc[11], f23.x, w3);
                ffma2(acc[12], f23.y, w0); ffma2(acc[13], f23.y, w1);
                ffma2(acc[14], f23.y, w2); ffma2(acc[15], f23.y, w3);
            }
        }
        __syncthreads();                 // protect feats before next phase writes
        pbase += P;
    }

    float4 g4  = ((const float4*)g_edge)[lane];
    float4 be4 = ((const float4*)be_edge)[lane];
    float4* o4 = (float4*)(out + E_OFF);
#pragma unroll
    for (int p = 0; p < 4; p++) {
        float2 u0 = unpack2(acc[p*4]);
        float2 u1 = unpack2(acc[p*4+1]);
        float2 u2 = unpack2(acc[p*4+2]);
        float2 u3 = unpack2(acc[p*4+3]);
        int e0 = 8*w + 2*p, e1 = e0 + 1;
        float4 tp0 = ((const float4*)g_Tpos)[sdc[e0]*32 + lane];
        float4 tp1 = ((const float4*)g_Tpos)[sdc[e1]*32 + lane];
        float4 a0 = make_float4(u0.x+tp0.x, u1.x+tp0.y, u2.x+tp0.z, u3.x+tp0.w);
        float4 a1 = make_float4(u0.y+tp1.x, u1.y+tp1.y, u2.y+tp1.z, u3.y+tp1.w);
        float4 r0v = ln128(a0, g4, be4);
        float4 r1v = ln128(a1, g4, be4);
        o4[(size_t)(ebase+e0)*32 + lane] = r0v;
        o4[(size_t)(ebase+e1)*32 + lane] = r1v;
    }
}

// ---------------- V node: features + GEMM(96->128, W via L1/L2) + fuse + LN ----------------
#define VN_SMF (96*64 + 64 + 192 + 36 + 192)   // 6628 floats = 26.5KB
__global__ __launch_bounds__(256, 3) void k_vnode(
    const float* __restrict__ Y, const int* __restrict__ Y_t, const int* __restrict__ pt,
    const float* __restrict__ g_node, const float* __restrict__ bn_node,
    float* __restrict__ out) {
    extern __shared__ float sm[];
    float* feats = sm;                    // [96][64]
    float* at    = sm + 96*64;            // [4][15] pad 64
    float* ys    = at + 64;               // [64][3]
    float* fr    = ys + 192;              // [4][9]
    int*   cols  = (int*)(fr + 36);       // [64][3]

    int t = threadIdx.x;
    int bid = blockIdx.x;
    int rbase = bid * 4;
    int rowg0 = bid * 64;
    int lane = t & 31, w = t >> 5;

    if (t < 60) at[t] = g_atoms[(size_t)rbase*15 + t];
    if (t < 192) ys[t] = Y[(size_t)rowg0*3 + t];
    if (t < 64) {
        int yt = Y_t[rowg0 + t];
        cols[t*3+0] = yt;
        cols[t*3+1] = 120 + pt[120 + yt];
        cols[t*3+2] = 139 + pt[240 + yt];
    }
    for (int idx = t; idx < 12*64; idx += 256) feats[84*64 + idx] = 0.0f;
    __syncthreads();
    if (t < 4) {
        const float* A = at + t*15;
        float v1x=A[0]-A[3], v1y=A[1]-A[4], v1z=A[2]-A[5];
        float v2x=A[6]-A[3], v2y=A[7]-A[4], v2z=A[8]-A[5];
        float n1 = sqrtf(v1x*v1x+v1y*v1y+v1z*v1z) + 1e-8f;
        float e1x=v1x/n1, e1y=v1y/n1, e1z=v1z/n1;
        float d12 = e1x*v2x + e1y*v2y + e1z*v2z;
        float ux=v2x-e1x*d12, uy=v2y-e1y*d12, uz=v2z-e1z*d12;
        float n2 = sqrtf(ux*ux+uy*uy+uz*uz) + 1e-8f;
        float e2x=ux/n2, e2y=uy/n2, e2z=uz/n2;
        float e3x=e1y*e2z-e1z*e2y, e3y=e1z*e2x-e1x*e2z, e3z=e1x*e2y-e1y*e2x;
        float* F = fr + t*9;
        F[0]=e1x;F[1]=e1y;F[2]=e1z; F[3]=e2x;F[4]=e2y;F[5]=e2z; F[6]=e3x;F[7]=e3y;F[8]=e3z;
    }
    {
        int row = t & 63, res = row >> 4;
        const float* yy = ys + row*3;
        for (int p = t >> 6; p < 5; p += 4) {
            const float* A = at + res*15 + p*3;
            float dx=A[0]-yy[0], dy=A[1]-yy[1], dz=A[2]-yy[2];
            float D = sqrtf(dx*dx+dy*dy+dz*dz + 1e-6f);
            rbf16(D, &feats[(p*16)*64 + row], 64);
        }
    }
    __syncthreads();
    if (t < 64) {
        int row = t, res = row >> 4;
        const float* F = fr + res*9;
        float dx = ys[row*3]   - at[res*15+3];
        float dy = ys[row*3+1] - at[res*15+4];
        float dz = ys[row*3+2] - at[res*15+5];
        float lv0 = F[0]*dx+F[1]*dy+F[2]*dz;
        float lv1 = F[3]*dx+F[4]*dy+F[5]*dz;
        float lv2 = F[6]*dx+F[7]*dy+F[8]*dz;
        float rxy  = sqrtf(lv0*lv0 + lv1*lv1 + 1e-8f);
        float rxyz = sqrtf(lv0*lv0 + lv1*lv1 + lv2*lv2) + 1e-8f;
        feats[80*64+row] = lv0/rxy;
        feats[81*64+row] = lv1/rxy;
        feats[82*64+row] = rxy/rxyz;
        feats[83*64+row] = lv2/rxyz;
    }
    __syncthreads();
    ull acc[16];
    {
        float4 b4 = ((const float4*)g_btf)[lane];
        ull b0 = pack2(b4.x), b1 = pack2(b4.y), b2 = pack2(b4.z), b3 = pack2(b4.w);
#pragma unroll
        for (int p = 0; p < 4; p++) { acc[p*4]=b0; acc[p*4+1]=b1; acc[p*4+2]=b2; acc[p*4+3]=b3; }
    }
    for (int kc = 0; kc < 6; kc++) {
        const float4* Wg = (const float4*)g_WdT2 + (size_t)kc*512 + lane;
        const float* fb = feats + (kc*16)*64 + 8*w;
#pragma unroll
        for (int fi = 0; fi < 16; fi++) {
            float4 w4 = __ldg(&Wg[fi*32]);
            ulonglong2 f01 = *(const ulonglong2*)&fb[fi*64];
            ulonglong2 f23 = *(const ulonglong2*)&fb[fi*64 + 4];
            ull w0 = pack2(w4.x), w1 = pack2(w4.y), w2 = pack2(w4.z), w3 = pack2(w4.w);
            ffma2(acc[0],  f01.x, w0); ffma2(acc[1],  f01.x, w1);
            ffma2(acc[2],  f01.x, w2); ffma2(acc[3],  f01.x, w3);
            ffma2(acc[4],  f01.y, w0); ffma2(acc[5],  f01.y, w1);
            ffma2(acc[6],  f01.y, w2); ffma2(acc[7],  f01.y, w3);
            ffma2(acc[8],  f23.x, w0); ffma2(acc[9],  f23.x, w1);
            ffma2(acc[10], f23.x, w2); ffma2(acc[11], f23.x, w3);
            ffma2(acc[12], f23.y, w0); ffma2(acc[13], f23.y, w1);
            ffma2(acc[14], f23.y, w2); ffma2(acc[15], f23.y, w3);
        }
    }
    float4 g4  = ((const float4*)g_node)[lane];
    float4 be4 = ((const float4*)bn_node)[lane];
    float4* o4 = (float4*)(out + V_OFF);
#pragma unroll
    for (int p = 0; p < 4; p++) {
        float2 u0 = unpack2(acc[p*4]);
        float2 u1 = unpack2(acc[p*4+1]);
        float2 u2 = unpack2(acc[p*4+2]);
        float2 u3 = unpack2(acc[p*4+3]);
        int e0 = 8*w + 2*p, e1 = e0 + 1;
        float4 a0 = make_float4(u0.x, u1.x, u2.x, u3.x);
        float4 a1 = make_float4(u0.y, u1.y, u2.y, u3.y);
#pragma unroll
        for (int j = 0; j < 3; j++) {
            float4 q0 = ((const float4*)g_Wfuse)[cols[e0*3+j]*32 + lane];
            float4 q1 = ((const float4*)g_Wfuse)[cols[e1*3+j]*32 + lane];
            a0.x+=q0.x; a0.y+=q0.y; a0.z+=q0.z; a0.w+=q0.w;
            a1.x+=q1.x; a1.y+=q1.y; a1.z+=q1.z; a1.w+=q1.w;
        }
        float4 r0v = ln128(a0, g4, be4);
        float4 r1v = ln128(a1, g4, be4);
        o4[(size_t)(rowg0+e0)*32 + lane] = r0v;
        o4[(size_t)(rowg0+e1)*32 + lane] = r1v;
    }
}

// ---------------- Y_nodes (gather + LN) + Y_m copy ----------------
__global__ __launch_bounds__(256) void k_ynode(
    const float* __restrict__ Y_m, const int* __restrict__ Y_t, const int* __restrict__ pt,
    const float* __restrict__ b_yn, const float* __restrict__ g_yn,
    const float* __restrict__ bn_yn, float* __restrict__ out) {
    int t = threadIdx.x, lane = t & 31, w = t >> 5;
    int row = blockIdx.x*8 + w;
    int yt = Y_t[row];
    int c0 = yt, c1 = 120 + pt[120+yt], c2 = 139 + pt[240+yt];
    float4 a  = ((const float4*)&g_WynT[(size_t)c0*128])[lane];
    float4 a1 = ((const float4*)&g_WynT[(size_t)c1*128])[lane];
    float4 a2 = ((const float4*)&g_WynT[(size_t)c2*128])[lane];
    float4 b4 = ((const float4*)b_yn)[lane];
    a.x += a1.x + a2.x + b4.x;
    a.y += a1.y + a2.y + b4.y;
    a.z += a1.z + a2.z + b4.z;
    a.w += a1.w + a2.w + b4.w;
    float4 g4  = ((const float4*)g_yn)[lane];
    float4 be4 = ((const float4*)bn_yn)[lane];
    float4 r = ln128(a, g4, be4);
    ((float4*)(out + YN_OFF))[(size_t)row*32 + lane] = r;
    if (lane == 0) out[YM_OFF + row] = Y_m[row];
}

// ---------------- Y_edges: symmetric pairs, 16->128 + LN ----------------
__global__ __launch_bounds__(256) void k_yedge(
    const float* __restrict__ Y, const float* __restrict__ W_ye,
    const float* __restrict__ b_ye, const float* __restrict__ g_ye,
    const float* __restrict__ bn_ye, float* __restrict__ out) {
    __shared__ float ys[48];
    __shared__ float rbfs[136*16];
    __shared__ float WyeS[16*128];
    __shared__ int sm1[136], sm2[136];
    int t = threadIdx.x, bl = blockIdx.x;
    if (t < 48) ys[t] = Y[(size_t)bl*48 + t];
    for (int i = t; i < 2048; i += 256) {
        int c = i >> 4, r = i & 15;
        WyeS[r*128 + c] = W_ye[i];
    }
    if (t < 136) {
        int u = t, m1 = 0;
        while (u >= 16 - m1) { u -= 16 - m1; m1++; }
        sm1[t] = m1; sm2[t] = m1 + u;
    }
    __syncthreads();
    if (t < 136) {
        int m1 = sm1[t], m2 = sm2[t];
        float dx = ys[m1*3]-ys[m2*3], dy = ys[m1*3+1]-ys[m2*3+1], dz = ys[m1*3+2]-ys[m2*3+2];
        float D = sqrtf(dx*dx + dy*dy + dz*dz + 1e-6f);
        rbf16(D, &rbfs[t*16], 1);
    }
    __syncthreads();
    int lane = t & 31, w = t >> 5;
    float4 bye4 = ((const float4*)b_ye)[lane];
    float4 g4   = ((const float4*)g_ye)[lane];
    float4 be4  = ((const float4*)bn_ye)[lane];
    float4* o4 = (float4*)out;
    size_t yebase4 = YE_OFF >> 2;
    for (int u = w; u < 136; u += 8) {
        float4 a = bye4;
#pragma unroll
        for (int r = 0; r < 16; r++) {
            float rb = rbfs[u*16 + r];
            float4 wv = ((const float4*)&WyeS[r*128])[lane];
            a.x = fmaf(rb, wv.x, a.x); a.y = fmaf(rb, wv.y, a.y);
            a.z = fmaf(rb, wv.z, a.z); a.w = fmaf(rb, wv.w, a.w);
        }
        float4 res = ln128(a, g4, be4);
        int m1 = sm1[u], m2 = sm2[u];
        size_t r1 = (size_t)bl*256 + m1*16 + m2;
        size_t r2 = (size_t)bl*256 + m2*16 + m1;
        o4[yebase4 + r1*32 + lane] = res;
        if (r2 != r1) o4[yebase4 + r2*32 + lane] = res;
    }
}

// ---------------- launch: multi-stream DAG; yedge overlapped with edge ----------------
extern "C" void kernel_launch(void* const* d_in, const int* in_sizes, int n_in,
                              void* d_out, int out_size) {
    const float* X        = (const float*)d_in[0];
    const float* Y        = (const float*)d_in[1];
    const float* Y_m      = (const float*)d_in[2];
    const float* mask     = (const float*)d_in[3];
    const float* W_pos    = (const float*)d_in[4];
    const float* b_pos    = (const float*)d_in[5];
    const float* W_edge   = (const float*)d_in[6];
    const float* b_edge   = (const float*)d_in[7];
    const float* g_edge   = (const float*)d_in[8];
    const float* be_edge  = (const float*)d_in[9];
    const float* W_down   = (const float*)d_in[10];
    const float* b_down   = (const float*)d_in[11];
    const float* g_node   = (const float*)d_in[12];
    const float* bn_node  = (const float*)d_in[13];
    const float* W_type   = (const float*)d_in[14];
    const float* b_type   = (const float*)d_in[15];
    const float* W_yn     = (const float*)d_in[16];
    const float* b_yn     = (const float*)d_in[17];
    const float* g_yn     = (const float*)d_in[18];
    const float* bn_yn    = (const float*)d_in[19];
    const float* W_ye     = (const float*)d_in[20];
    const float* b_ye     = (const float*)d_in[21];
    const float* g_ye     = (const float*)d_in[22];
    const float* bn_ye    = (const float*)d_in[23];
    const int*   Y_t      = (const int*)d_in[24];
    const int*   R_idx    = (const int*)d_in[25];
    const int*   chains   = (const int*)d_in[26];
    const int*   pt       = (const int*)d_in[27];
    float* out = (float*)d_out;

    static bool init_done = false;
    static cudaStream_t s2, s3;
    static cudaEvent_t evRoot, evAtoms, evTF, evTopk, evS2, evS3;
    if (!init_done) {
        cudaStreamCreateWithFlags(&s2, cudaStreamNonBlocking);
        cudaStreamCreateWithFlags(&s3, cudaStreamNonBlocking);
        cudaEventCreateWithFlags(&evRoot,  cudaEventDisableTiming);
        cudaEventCreateWithFlags(&evAtoms, cudaEventDisableTiming);
        cudaEventCreateWithFlags(&evTF,    cudaEventDisableTiming);
        cudaEventCreateWithFlags(&evTopk,  cudaEventDisableTiming);
        cudaEventCreateWithFlags(&evS2,    cudaEventDisableTiming);
        cudaEventCreateWithFlags(&evS3,    cudaEventDisableTiming);
        cudaFuncSetAttribute(k_edge,  cudaFuncAttributeMaxDynamicSharedMemorySize, EDGE_SMF*4);
        cudaFuncSetAttribute(k_vnode, cudaFuncAttributeMaxDynamicSharedMemorySize, VN_SMF*4);
        init_done = true;
    }

    // fork from origin stream
    cudaEventRecord(evRoot, 0);
    cudaStreamWaitEvent(s2, evRoot, 0);
    cudaStreamWaitEvent(s3, evRoot, 0);

    // s2: weight prep chain + ynode (runs concurrent with topk)
    k_trans<<<(416*128 + 148*128 + 96*128 + 147*128 + 255)/256, 256, 0, s2>>>(W_edge, W_down, W_yn);
    k_fuse<<<(66*128 + 147*128 + 128 + 255)/256, 256, 0, s2>>>(W_pos, b_pos, W_edge, W_type, b_type, b_down);
    cudaEventRecord(evTF, s2);
    k_ynode<<<NROW/8, 256, 0, s2>>>(Y_m, Y_t, pt, b_yn, g_yn, bn_yn, out);

    // s0: geometry chain
    k_atoms<<<NRES/256, 256>>>(X);
    cudaEventRecord(evAtoms, 0);

    // s2: vnode needs atoms + trans + fuse (runs concurrent with topk/edge)
    cudaStreamWaitEvent(s2, evAtoms, 0);
    k_vnode<<<NROW/64, 256, VN_SMF*4, s2>>>(Y, Y_t, pt, g_node, bn_node, out);
    cudaEventRecord(evS2, s2);

    // s0: topk then edge (edge also needs trans+fuse)
    k_topk<<<NRES, 256, 0, 0>>>(mask, out);
    cudaEventRecord(evTopk, 0);
    cudaStreamWaitEvent(0, evTF, 0);
    k_edge<<<NEDGE/64, 256, EDGE_SMF*4, 0>>>(R_idx, chains, b_edge, g_edge, be_edge, out);

    // s3: yedge delayed to co-run with edge (DRAM-bound vs FMA-bound)
    cudaStreamWaitEvent(s3, evTopk, 0);
    k_yedge<<<BB*LLEN, 256, 0, s3>>>(Y, W_ye, b_ye, g_ye, bn_ye, out);
    cudaEventRecord(evS3, s3);

    // join
    cudaStreamWaitEvent(0, evS2, 0);
    cudaStreamWaitEvent(0, evS3, 0);
}